// round 1
// baseline (speedup 1.0000x reference)
#include <cuda_runtime.h>
#include <cstdint>
#include <cstddef>

#define B_   2
#define S_   2048
#define D_   2048
#define QC_  16
#define KVC_ 4
#define HD_  128
#define FF_  8192
#define M_   (B_ * S_)            // 4096 rows
#define QKVN (D_ + 2 * KVC_ * HD_) // 3072

// ---------------- scratch (device globals: allocation-free) ----------------
__device__ float g_xn  [(size_t)M_ * D_];
__device__ float g_qkv [(size_t)M_ * QKVN];
__device__ float g_q   [(size_t)B_ * QC_  * S_ * HD_];
__device__ float g_k   [(size_t)B_ * KVC_ * S_ * HD_];
__device__ float g_v   [(size_t)B_ * KVC_ * S_ * HD_];
__device__ float g_attn[(size_t)M_ * D_];
__device__ float g_x1  [(size_t)M_ * D_];
__device__ float g_h   [(size_t)M_ * FF_];

// ---------------- RMSNorm: one block per row of 2048 ----------------
__global__ __launch_bounds__(256) void rmsnorm_kernel(
    const float* __restrict__ x, const float* __restrict__ w, float* __restrict__ out)
{
    const int row = blockIdx.x;
    const int tid = threadIdx.x;
    const float4* xr = (const float4*)(x + (size_t)row * D_);
    float4 vals[2];
    float ss = 0.f;
#pragma unroll
    for (int i = 0; i < 2; i++) {
        float4 v = xr[tid + 256 * i];
        vals[i] = v;
        ss += v.x * v.x + v.y * v.y + v.z * v.z + v.w * v.w;
    }
#pragma unroll
    for (int sh = 16; sh > 0; sh >>= 1) ss += __shfl_xor_sync(0xffffffffu, ss, sh);
    __shared__ float red[8];
    if ((tid & 31) == 0) red[tid >> 5] = ss;
    __syncthreads();
    float tot = 0.f;
#pragma unroll
    for (int i = 0; i < 8; i++) tot += red[i];
    const float rs = rsqrtf(tot * (1.f / (float)D_) + 1e-5f);
    const float4* w4 = (const float4*)w;
    float4* o4 = (float4*)(out + (size_t)row * D_);
#pragma unroll
    for (int i = 0; i < 2; i++) {
        float4 v = vals[i], ww = w4[tid + 256 * i];
        float4 r;
        r.x = v.x * rs * ww.x; r.y = v.y * rs * ww.y;
        r.z = v.z * rs * ww.z; r.w = v.w * rs * ww.w;
        o4[tid + 256 * i] = r;
    }
}

// ---------------- RoPE + layout: one block per token ----------------
__global__ __launch_bounds__(256) void rope_kernel(
    const float* __restrict__ qkv, const float* __restrict__ rsin,
    const float* __restrict__ rcos, float* __restrict__ q,
    float* __restrict__ k, float* __restrict__ v)
{
    const int t = blockIdx.x;           // b*S + s
    const int b = t / S_;
    const int s = t % S_;
    const int tid = threadIdx.x;
    const float* row = qkv + (size_t)t * QKVN;
    const float* sinr = rsin + (size_t)s * HD_;
    const float* cosr = rcos + (size_t)s * HD_;

    // Q: 1024 pairs (16 heads x 64 pairs)
    for (int p = tid; p < 1024; p += 256) {
        const int h  = p >> 6;
        const int pp = p & 63;
        const float x0 = row[2 * p], x1 = row[2 * p + 1];
        const float sn = sinr[2 * pp], cs = cosr[2 * pp];
        const size_t o = (((size_t)(b * QC_ + h)) * S_ + s) * HD_ + 2 * pp;
        q[o]     = x0 * cs - x1 * sn;
        q[o + 1] = x1 * cs + x0 * sn;
    }
    // K: 256 pairs (4 heads x 64), pre-scale by HD^-0.5
    const float khs = 0.08838834764831845f; // 1/sqrt(128)
    for (int p = tid; p < 256; p += 256) {
        const int h  = p >> 6;
        const int pp = p & 63;
        const float x0 = row[D_ + 2 * p], x1 = row[D_ + 2 * p + 1];
        const float sn = sinr[2 * pp], cs = cosr[2 * pp];
        const size_t o = (((size_t)(b * KVC_ + h)) * S_ + s) * HD_ + 2 * pp;
        k[o]     = (x0 * cs - x1 * sn) * khs;
        k[o + 1] = (x1 * cs + x0 * sn) * khs;
    }
    // V: copy 512
    for (int e = tid; e < 512; e += 256) {
        const int h = e >> 7;
        const int d = e & 127;
        v[(((size_t)(b * KVC_ + h)) * S_ + s) * HD_ + d] = row[D_ + 512 + e];
    }
}

// ---------------- 128x128x16 fp32 GEMM, fused epilogues ----------------
// EPI: 0 = C = A@B ; 1 = C = A@B + R ; 2 = C = square(relu(A@B))
template <int EPI>
__global__ __launch_bounds__(256) void gemm_kernel(
    const float* __restrict__ A, const float* __restrict__ Bm,
    const float* __restrict__ R, float* __restrict__ C,
    int M, int N, int K)
{
    __shared__ float As[16][132];
    __shared__ float Bs[16][132];
    const int tid = threadIdx.x;
    const int tx  = tid & 15;
    const int ty  = tid >> 4;
    const int bm  = blockIdx.y * 128;
    const int bn  = blockIdx.x * 128;

    const int arow = tid >> 2;
    const int acol = (tid & 3) << 2;
    const int brow = tid >> 5;
    const int bcol = (tid & 31) << 2;

    const float* Ap = A + (size_t)(bm + arow) * K + acol;
    const float* Bp = Bm + (size_t)brow * N + bn + bcol;

    float acc[8][8];
#pragma unroll
    for (int i = 0; i < 8; i++)
#pragma unroll
        for (int j = 0; j < 8; j++) acc[i][j] = 0.f;

    for (int k0 = 0; k0 < K; k0 += 16) {
        const float4 a0 = *(const float4*)(Ap);
        const float4 a1 = *(const float4*)(Ap + (size_t)64 * K);
        const float4 b0 = *(const float4*)(Bp);
        const float4 b1 = *(const float4*)(Bp + (size_t)8 * N);
        As[acol + 0][arow] = a0.x; As[acol + 1][arow] = a0.y;
        As[acol + 2][arow] = a0.z; As[acol + 3][arow] = a0.w;
        As[acol + 0][arow + 64] = a1.x; As[acol + 1][arow + 64] = a1.y;
        As[acol + 2][arow + 64] = a1.z; As[acol + 3][arow + 64] = a1.w;
        *(float4*)&Bs[brow][bcol]     = b0;
        *(float4*)&Bs[brow + 8][bcol] = b1;
        __syncthreads();
#pragma unroll
        for (int kk = 0; kk < 16; kk++) {
            float a[8], b[8];
            *(float4*)(a)     = *(const float4*)&As[kk][ty * 4];
            *(float4*)(a + 4) = *(const float4*)&As[kk][ty * 4 + 64];
            *(float4*)(b)     = *(const float4*)&Bs[kk][tx * 4];
            *(float4*)(b + 4) = *(const float4*)&Bs[kk][tx * 4 + 64];
#pragma unroll
            for (int i = 0; i < 8; i++)
#pragma unroll
                for (int j = 0; j < 8; j++)
                    acc[i][j] += a[i] * b[j];
        }
        __syncthreads();
        Ap += 16;
        Bp += (size_t)16 * N;
    }

#pragma unroll
    for (int i = 0; i < 8; i++) {
        const int r = bm + ty * 4 + (i & 3) + (i >> 2) * 64;
#pragma unroll
        for (int jg = 0; jg < 2; jg++) {
            const int c = bn + tx * 4 + jg * 64;
            float4 v;
            v.x = acc[i][jg * 4 + 0]; v.y = acc[i][jg * 4 + 1];
            v.z = acc[i][jg * 4 + 2]; v.w = acc[i][jg * 4 + 3];
            if (EPI == 1) {
                const float4 rv = *(const float4*)(R + (size_t)r * N + c);
                v.x += rv.x; v.y += rv.y; v.z += rv.z; v.w += rv.w;
            } else if (EPI == 2) {
                v.x = fmaxf(v.x, 0.f); v.x *= v.x;
                v.y = fmaxf(v.y, 0.f); v.y *= v.y;
                v.z = fmaxf(v.z, 0.f); v.z *= v.z;
                v.w = fmaxf(v.w, 0.f); v.w *= v.w;
            }
            *(float4*)(C + (size_t)r * N + c) = v;
        }
    }
}

// ---------------- causal flash attention, Br=Bc=64, fp32 ----------------
// grid: (S/64, QC, B), block 256.  smem XOR-swizzled (d4phys = d4 ^ (row&31))
#define FLASH_SMEM ((3 * 64 * 128 + 64 * 68) * 4)

__global__ __launch_bounds__(256) void flash_kernel(
    const float* __restrict__ gq, const float* __restrict__ gk,
    const float* __restrict__ gv, float* __restrict__ go)
{
    extern __shared__ float sm[];
    float* Qs = sm;
    float* Ks = sm + 64 * 128;
    float* Vs = sm + 2 * 64 * 128;
    float* Ps = sm + 3 * 64 * 128;   // [64][68]

    const int tid = threadIdx.x;
    const int tx  = tid & 15;
    const int ty  = tid >> 4;
    const int qt  = blockIdx.x;
    const int h   = blockIdx.y;
    const int b   = blockIdx.z;
    const int kvh = h & 3;

    const float* qbase = gq + (((size_t)(b * QC_ + h)) * S_ + qt * 64) * HD_;
    const float* kbase = gk + ((size_t)(b * KVC_ + kvh)) * S_ * HD_;
    const float* vbase = gv + ((size_t)(b * KVC_ + kvh)) * S_ * HD_;

#pragma unroll
    for (int i = 0; i < 8; i++) {
        const int off = i * 1024 + tid * 4;
        const int r  = off >> 7;
        const int d4 = (off & 127) >> 2;
        *(float4*)(Qs + r * 128 + ((d4 ^ (r & 31)) << 2)) = *(const float4*)(qbase + off);
    }

    float o[4][8];
    float m[4], l[4];
#pragma unroll
    for (int i = 0; i < 4; i++) {
        m[i] = -1e30f; l[i] = 0.f;
#pragma unroll
        for (int j = 0; j < 8; j++) o[i][j] = 0.f;
    }

    const int rowq[4] = { ty, ty + 16, ty + 32, ty + 48 };
    const int rowk[4] = { tx, tx + 16, tx + 32, tx + 48 };

    for (int kt = 0; kt <= qt; kt++) {
        __syncthreads();
#pragma unroll
        for (int i = 0; i < 8; i++) {
            const int off = i * 1024 + tid * 4;
            const int r  = off >> 7;
            const int d4 = (off & 127) >> 2;
            const int sw = r * 128 + ((d4 ^ (r & 31)) << 2);
            *(float4*)(Ks + sw) = *(const float4*)(kbase + (size_t)kt * 64 * HD_ + off);
            *(float4*)(Vs + sw) = *(const float4*)(vbase + (size_t)kt * 64 * HD_ + off);
        }
        __syncthreads();

        float s[4][4] = {};
#pragma unroll 4
        for (int d4 = 0; d4 < 32; d4++) {
            float4 q4[4], k4[4];
#pragma unroll
            for (int i = 0; i < 4; i++)
                q4[i] = *(const float4*)(Qs + rowq[i] * 128 + ((d4 ^ (rowq[i] & 31)) << 2));
#pragma unroll
            for (int j = 0; j < 4; j++)
                k4[j] = *(const float4*)(Ks + rowk[j] * 128 + ((d4 ^ (rowk[j] & 31)) << 2));
#pragma unroll
            for (int i = 0; i < 4; i++)
#pragma unroll
                for (int j = 0; j < 4; j++)
                    s[i][j] += q4[i].x * k4[j].x + q4[i].y * k4[j].y
                             + q4[i].z * k4[j].z + q4[i].w * k4[j].w;
        }

        if (kt == qt) {
#pragma unroll
            for (int i = 0; i < 4; i++)
#pragma unroll
                for (int j = 0; j < 4; j++)
                    if (rowk[j] > rowq[i]) s[i][j] -= 1e9f;
        }

#pragma unroll
        for (int i = 0; i < 4; i++) {
            float mx = fmaxf(fmaxf(s[i][0], s[i][1]), fmaxf(s[i][2], s[i][3]));
#pragma unroll
            for (int sh = 1; sh < 16; sh <<= 1)
                mx = fmaxf(mx, __shfl_xor_sync(0xffffffffu, mx, sh));
            const float mn = fmaxf(m[i], mx);
            const float sc = __expf(m[i] - mn);
            m[i] = mn;
            float rs = 0.f;
#pragma unroll
            for (int j = 0; j < 4; j++) {
                const float p = __expf(s[i][j] - mn);
                s[i][j] = p;
                rs += p;
            }
#pragma unroll
            for (int sh = 1; sh < 16; sh <<= 1)
                rs += __shfl_xor_sync(0xffffffffu, rs, sh);
            l[i] = l[i] * sc + rs;
#pragma unroll
            for (int j = 0; j < 8; j++) o[i][j] *= sc;
#pragma unroll
            for (int j = 0; j < 4; j++)
                Ps[rowq[i] * 68 + rowk[j]] = s[i][j];
        }
        __syncthreads();

#pragma unroll 2
        for (int jk = 0; jk < 64; jk++) {
            const float4 va = *(const float4*)(Vs + jk * 128 + ((tx        ^ (jk & 31)) << 2));
            const float4 vb = *(const float4*)(Vs + jk * 128 + (((tx + 16) ^ (jk & 31)) << 2));
#pragma unroll
            for (int i = 0; i < 4; i++) {
                const float p = Ps[rowq[i] * 68 + jk];
                o[i][0] += p * va.x; o[i][1] += p * va.y;
                o[i][2] += p * va.z; o[i][3] += p * va.w;
                o[i][4] += p * vb.x; o[i][5] += p * vb.y;
                o[i][6] += p * vb.z; o[i][7] += p * vb.w;
            }
        }
    }

#pragma unroll
    for (int i = 0; i < 4; i++) {
        const float inv = 1.f / l[i];
        const int srow = qt * 64 + rowq[i];
        float* dst = go + ((size_t)b * S_ + srow) * D_ + h * HD_;
        float4 va, vb;
        va.x = o[i][0] * inv; va.y = o[i][1] * inv; va.z = o[i][2] * inv; va.w = o[i][3] * inv;
        vb.x = o[i][4] * inv; vb.y = o[i][5] * inv; vb.z = o[i][6] * inv; vb.w = o[i][7] * inv;
        *(float4*)(dst + 4 * tx)      = va;
        *(float4*)(dst + 64 + 4 * tx) = vb;
    }
}

// ---------------- launcher ----------------
extern "C" void kernel_launch(void* const* d_in, const int* in_sizes, int n_in,
                              void* d_out, int out_size)
{
    (void)in_sizes; (void)n_in; (void)out_size;
    const float* x    = (const float*)d_in[0];
    // d_in[1] = mask: causal structure handled analytically (exact: exp underflow)
    const float* rsin = (const float*)d_in[2];
    const float* rcos = (const float*)d_in[3];
    const float* wqkv = (const float*)d_in[4];
    const float* wo   = (const float*)d_in[5];
    const float* n1   = (const float*)d_in[6];
    const float* n2   = (const float*)d_in[7];
    const float* wk   = (const float*)d_in[8];
    const float* wv   = (const float*)d_in[9];
    float* out = (float*)d_out;

    float *p_xn, *p_qkv, *p_q, *p_k, *p_v, *p_attn, *p_x1, *p_h;
    cudaGetSymbolAddress((void**)&p_xn,   g_xn);
    cudaGetSymbolAddress((void**)&p_qkv,  g_qkv);
    cudaGetSymbolAddress((void**)&p_q,    g_q);
    cudaGetSymbolAddress((void**)&p_k,    g_k);
    cudaGetSymbolAddress((void**)&p_v,    g_v);
    cudaGetSymbolAddress((void**)&p_attn, g_attn);
    cudaGetSymbolAddress((void**)&p_x1,   g_x1);
    cudaGetSymbolAddress((void**)&p_h,    g_h);

    cudaFuncSetAttribute(flash_kernel, cudaFuncAttributeMaxDynamicSharedMemorySize, FLASH_SMEM);

    // x1 = x + attn(rmsnorm(x))
    rmsnorm_kernel<<<M_, 256>>>(x, n1, p_xn);
    gemm_kernel<0><<<dim3(QKVN / 128, M_ / 128), 256>>>(p_xn, wqkv, nullptr, p_qkv, M_, QKVN, D_);
    rope_kernel<<<M_, 256>>>(p_qkv, rsin, rcos, p_q, p_k, p_v);
    flash_kernel<<<dim3(S_ / 64, QC_, B_), 256, FLASH_SMEM>>>(p_q, p_k, p_v, p_attn);
    gemm_kernel<1><<<dim3(D_ / 128, M_ / 128), 256>>>(p_attn, wo, x, p_x1, M_, D_, D_);

    // out = x1 + ffn(rmsnorm(x1))
    rmsnorm_kernel<<<M_, 256>>>(p_x1, n2, p_xn);
    gemm_kernel<2><<<dim3(FF_ / 128, M_ / 128), 256>>>(p_xn, wk, nullptr, p_h, M_, FF_, D_);
    gemm_kernel<1><<<dim3(D_ / 128, M_ / 128), 256>>>(p_h, wv, p_x1, out, M_, D_, FF_);
}

// round 3
// speedup vs baseline: 2.1911x; 2.1911x over previous
#include <cuda_runtime.h>
#include <cuda_bf16.h>
#include <cstdint>
#include <cstddef>

#define B_   2
#define S_   2048
#define D_   2048
#define QC_  16
#define KVC_ 4
#define HD_  128
#define FF_  8192
#define M_   (B_ * S_)             // 4096
#define QKVN (D_ + 2 * KVC_ * HD_) // 3072

// ---------------- scratch ----------------
__device__ float g_qkv [(size_t)M_ * QKVN];
__device__ float g_q   [(size_t)B_ * QC_  * S_ * HD_];
__device__ float g_k   [(size_t)B_ * KVC_ * S_ * HD_];
__device__ float g_v   [(size_t)B_ * KVC_ * S_ * HD_];
__device__ float g_x1  [(size_t)M_ * D_];
__device__ __nv_bfloat16 g_xn_hi [(size_t)M_ * D_];
__device__ __nv_bfloat16 g_xn_lo [(size_t)M_ * D_];
__device__ __nv_bfloat16 g_at_hi [(size_t)M_ * D_];
__device__ __nv_bfloat16 g_at_lo [(size_t)M_ * D_];
__device__ __nv_bfloat16 g_h_hi  [(size_t)M_ * FF_];
__device__ __nv_bfloat16 g_h_lo  [(size_t)M_ * FF_];
__device__ __nv_bfloat16 g_wqkv_hi[(size_t)QKVN * D_];
__device__ __nv_bfloat16 g_wqkv_lo[(size_t)QKVN * D_];
__device__ __nv_bfloat16 g_wo_hi [(size_t)D_ * D_];
__device__ __nv_bfloat16 g_wo_lo [(size_t)D_ * D_];
__device__ __nv_bfloat16 g_wk_hi [(size_t)FF_ * D_];
__device__ __nv_bfloat16 g_wk_lo [(size_t)FF_ * D_];
__device__ __nv_bfloat16 g_wv_hi [(size_t)D_ * FF_];
__device__ __nv_bfloat16 g_wv_lo [(size_t)D_ * FF_];

// ---------------- helpers ----------------
__device__ __forceinline__ uint32_t smem_u32(const void* p) {
    uint32_t a;
    asm("{ .reg .u64 t; cvta.to.shared.u64 t, %1; cvt.u32.u64 %0, t; }" : "=r"(a) : "l"(p));
    return a;
}
__device__ __forceinline__ void split_bf(float v, __nv_bfloat16& h, __nv_bfloat16& l) {
    h = __float2bfloat16(v);
    l = __float2bfloat16(v - __bfloat162float(h));
}

#define SW(o) (((uint32_t)(o)) ^ ((((uint32_t)(o)) >> 3) & 0x70u))

__device__ __forceinline__ void ldsm4(uint32_t* r, uint32_t addr) {
    asm volatile("ldmatrix.sync.aligned.m8n8.x4.shared.b16 {%0,%1,%2,%3},[%4];"
                 : "=r"(r[0]), "=r"(r[1]), "=r"(r[2]), "=r"(r[3]) : "r"(addr));
}
__device__ __forceinline__ void ldsm2(uint32_t* r, uint32_t addr) {
    asm volatile("ldmatrix.sync.aligned.m8n8.x2.shared.b16 {%0,%1},[%2];"
                 : "=r"(r[0]), "=r"(r[1]) : "r"(addr));
}
__device__ __forceinline__ void hmma(float* c, const uint32_t* a, const uint32_t* b) {
    asm volatile("mma.sync.aligned.m16n8k16.row.col.f32.bf16.bf16.f32 "
                 "{%0,%1,%2,%3},{%4,%5,%6,%7},{%8,%9},{%0,%1,%2,%3};"
                 : "+f"(c[0]), "+f"(c[1]), "+f"(c[2]), "+f"(c[3])
                 : "r"(a[0]), "r"(a[1]), "r"(a[2]), "r"(a[3]), "r"(b[0]), "r"(b[1]));
}

// ---------------- RMSNorm -> bf16 hi/lo ----------------
__global__ __launch_bounds__(256) void rmsnorm_bf_kernel(
    const float* __restrict__ x, const float* __restrict__ w,
    __nv_bfloat16* __restrict__ ohi, __nv_bfloat16* __restrict__ olo)
{
    const int row = blockIdx.x;
    const int tid = threadIdx.x;
    const float4* xr = (const float4*)(x + (size_t)row * D_);
    float4 vals[2];
    float ss = 0.f;
#pragma unroll
    for (int i = 0; i < 2; i++) {
        float4 v = xr[tid + 256 * i];
        vals[i] = v;
        ss += v.x * v.x + v.y * v.y + v.z * v.z + v.w * v.w;
    }
#pragma unroll
    for (int sh = 16; sh > 0; sh >>= 1) ss += __shfl_xor_sync(0xffffffffu, ss, sh);
    __shared__ float red[8];
    if ((tid & 31) == 0) red[tid >> 5] = ss;
    __syncthreads();
    float tot = 0.f;
#pragma unroll
    for (int i = 0; i < 8; i++) tot += red[i];
    const float rs = rsqrtf(tot * (1.f / (float)D_) + 1e-5f);
    const float4* w4 = (const float4*)w;
#pragma unroll
    for (int i = 0; i < 2; i++) {
        float4 v = vals[i], ww = w4[tid + 256 * i];
        float r[4] = { v.x * rs * ww.x, v.y * rs * ww.y, v.z * rs * ww.z, v.w * rs * ww.w };
        const size_t base = (size_t)row * D_ + (tid + 256 * i) * 4;
#pragma unroll
        for (int j = 0; j < 4; j++) {
            __nv_bfloat16 h, l;
            split_bf(r[j], h, l);
            ohi[base + j] = h;
            olo[base + j] = l;
        }
    }
}

// ---------------- weight transpose + split: W[K,N]f32 -> Wt[N,K] bf16 hi/lo ----
__global__ __launch_bounds__(256) void wsplit_kernel(
    const float* __restrict__ W, __nv_bfloat16* __restrict__ hi,
    __nv_bfloat16* __restrict__ lo, int K, int N)
{
    __shared__ float t[32][33];
    const int tx = threadIdx.x, ty = threadIdx.y;
    const int n0 = blockIdx.x * 32, k0 = blockIdx.y * 32;
#pragma unroll
    for (int j = 0; j < 4; j++)
        t[ty + 8 * j][tx] = W[(size_t)(k0 + ty + 8 * j) * N + n0 + tx];
    __syncthreads();
#pragma unroll
    for (int j = 0; j < 4; j++) {
        const float v = t[tx][ty + 8 * j];
        __nv_bfloat16 h, l;
        split_bf(v, h, l);
        const size_t o = (size_t)(n0 + ty + 8 * j) * K + k0 + tx;
        hi[o] = h;
        lo[o] = l;
    }
}

// ---------------- RoPE ----------------
__global__ __launch_bounds__(256) void rope_kernel(
    const float* __restrict__ qkv, const float* __restrict__ rsin,
    const float* __restrict__ rcos, float* __restrict__ q,
    float* __restrict__ k, float* __restrict__ v)
{
    const int t = blockIdx.x;
    const int b = t / S_;
    const int s = t % S_;
    const int tid = threadIdx.x;
    const float* row = qkv + (size_t)t * QKVN;
    const float* sinr = rsin + (size_t)s * HD_;
    const float* cosr = rcos + (size_t)s * HD_;
    for (int p = tid; p < 1024; p += 256) {
        const int h = p >> 6, pp = p & 63;
        const float x0 = row[2 * p], x1 = row[2 * p + 1];
        const float sn = sinr[2 * pp], cs = cosr[2 * pp];
        const size_t o = (((size_t)(b * QC_ + h)) * S_ + s) * HD_ + 2 * pp;
        q[o] = x0 * cs - x1 * sn;
        q[o + 1] = x1 * cs + x0 * sn;
    }
    const float khs = 0.08838834764831845f;
    for (int p = tid; p < 256; p += 256) {
        const int h = p >> 6, pp = p & 63;
        const float x0 = row[D_ + 2 * p], x1 = row[D_ + 2 * p + 1];
        const float sn = sinr[2 * pp], cs = cosr[2 * pp];
        const size_t o = (((size_t)(b * KVC_ + h)) * S_ + s) * HD_ + 2 * pp;
        k[o] = (x0 * cs - x1 * sn) * khs;
        k[o + 1] = (x1 * cs + x0 * sn) * khs;
    }
    for (int e = tid; e < 512; e += 256) {
        const int h = e >> 7, d = e & 127;
        v[(((size_t)(b * KVC_ + h)) * S_ + s) * HD_ + d] = row[D_ + 512 + e];
    }
}

// ---------------- HMMA GEMM: C[M,N] = A[M,K] @ Wt[N,K]^T, 3xBF16 fused ----------
// CTA 128x128, 8 warps (warp 64x32), cp.async 3-stage, fused hi/lo chunk loads.
// EPI 0: Cf = acc ; EPI 1: Cf = acc + R ; EPI 2: (Chi,Clo) = split(relu(acc)^2)
#define PIPE 3
#define STG  65536
#define GEMM_SMEM (PIPE * STG)

template <int EPI>
__global__ __launch_bounds__(256) void mma_gemm(
    const __nv_bfloat16* __restrict__ Ahi, const __nv_bfloat16* __restrict__ Alo,
    const __nv_bfloat16* __restrict__ Bhi, const __nv_bfloat16* __restrict__ Blo,
    const float* __restrict__ R, float* __restrict__ Cf,
    __nv_bfloat16* __restrict__ Chi, __nv_bfloat16* __restrict__ Clo,
    int N, int K)
{
    extern __shared__ char smem[];
    const uint32_t sb = smem_u32(smem);
    const int tid = threadIdx.x;
    const int wid = tid >> 5, lane = tid & 31;
    const int wm = wid & 1, wn = wid >> 1;
    const int bm = blockIdx.y * 128, bn = blockIdx.x * 128;
    const int NC = K >> 6;

    float acc[4][4][4];
#pragma unroll
    for (int i = 0; i < 4; i++)
#pragma unroll
        for (int j = 0; j < 4; j++)
#pragma unroll
            for (int q = 0; q < 4; q++) acc[i][j][q] = 0.f;

    const uint32_t u16 = (tid & 7) << 4;

    auto issue = [&](int c) {
        if (c < NC) {
            const int kc = c << 6;
            const uint32_t st = sb + (uint32_t)(c % PIPE) * STG;
            const char* pa_hi = (const char*)(Ahi + (size_t)bm * K + kc);
            const char* pa_lo = (const char*)(Alo + (size_t)bm * K + kc);
            const char* pb_hi = (const char*)(Bhi + (size_t)bn * K + kc);
            const char* pb_lo = (const char*)(Blo + (size_t)bn * K + kc);
#pragma unroll
            for (int i = 0; i < 4; i++) {
                const int r = (tid >> 3) + 32 * i;
                const uint32_t so = SW(r * 128 + u16);
                const size_t go = (size_t)r * (K * 2) + u16;
                asm volatile("cp.async.cg.shared.global [%0],[%1],16;"
                             :: "r"(st + so), "l"(pa_hi + go));
                asm volatile("cp.async.cg.shared.global [%0],[%1],16;"
                             :: "r"(st + 16384 + so), "l"(pa_lo + go));
                asm volatile("cp.async.cg.shared.global [%0],[%1],16;"
                             :: "r"(st + 32768 + so), "l"(pb_hi + go));
                asm volatile("cp.async.cg.shared.global [%0],[%1],16;"
                             :: "r"(st + 49152 + so), "l"(pb_lo + go));
            }
        }
        asm volatile("cp.async.commit_group;");
    };

    for (int c = 0; c < PIPE; c++) issue(c);

    // ldmatrix lane-invariant address pieces
    const int arow = wm * 64 + (lane & 15);
    const uint32_t axo = ((uint32_t)arow & 7) << 4;
    const uint32_t akh = ((uint32_t)lane >> 4) << 4;
    const int brow = wn * 32 + (lane & 7);
    const uint32_t bxo = ((uint32_t)brow & 7) << 4;
    const uint32_t bkh = (((uint32_t)lane >> 3) & 1) << 4;

    for (int c = 0; c < NC; c++) {
        asm volatile("cp.async.wait_group %0;" :: "n"(PIPE - 1) : "memory");
        __syncthreads();
        const uint32_t st = sb + (uint32_t)(c % PIPE) * STG;
#pragma unroll
        for (int ks = 0; ks < 4; ks++) {
            const uint32_t kb = (uint32_t)ks * 32;
            uint32_t ah[4][4], al[4][4], bh[4][2], bl[4][2];
#pragma unroll
            for (int mt = 0; mt < 4; mt++) {
                const uint32_t off = (uint32_t)(arow + mt * 16) * 128 + ((kb + akh) ^ axo);
                ldsm4(ah[mt], st + off);
                ldsm4(al[mt], st + 16384 + off);
            }
#pragma unroll
            for (int nt = 0; nt < 4; nt++) {
                const uint32_t off = (uint32_t)(brow + nt * 8) * 128 + ((kb + bkh) ^ bxo);
                ldsm2(bh[nt], st + 32768 + off);
                ldsm2(bl[nt], st + 49152 + off);
            }
#pragma unroll
            for (int mt = 0; mt < 4; mt++)
#pragma unroll
                for (int nt = 0; nt < 4; nt++) {
                    hmma(acc[mt][nt], ah[mt], bh[nt]);
                    hmma(acc[mt][nt], al[mt], bh[nt]);
                    hmma(acc[mt][nt], ah[mt], bl[nt]);
                }
        }
        __syncthreads();
        issue(c + PIPE);
    }

    // epilogue
    const int row0 = bm + wm * 64 + (lane >> 2);
    const int col0 = bn + wn * 32 + ((lane & 3) << 1);
#pragma unroll
    for (int mt = 0; mt < 4; mt++) {
#pragma unroll
        for (int nt = 0; nt < 4; nt++) {
            const int r0 = row0 + mt * 16;
            const int cc = col0 + nt * 8;
            if (EPI <= 1) {
                float2 v0 = make_float2(acc[mt][nt][0], acc[mt][nt][1]);
                float2 v1 = make_float2(acc[mt][nt][2], acc[mt][nt][3]);
                if (EPI == 1) {
                    const float2 ra = *(const float2*)(R + (size_t)r0 * N + cc);
                    const float2 rb = *(const float2*)(R + (size_t)(r0 + 8) * N + cc);
                    v0.x += ra.x; v0.y += ra.y;
                    v1.x += rb.x; v1.y += rb.y;
                }
                *(float2*)(Cf + (size_t)r0 * N + cc) = v0;
                *(float2*)(Cf + (size_t)(r0 + 8) * N + cc) = v1;
            } else {
#pragma unroll
                for (int half = 0; half < 2; half++) {
                    float v0 = acc[mt][nt][2 * half + 0];
                    float v1 = acc[mt][nt][2 * half + 1];
                    v0 = fmaxf(v0, 0.f); v0 *= v0;
                    v1 = fmaxf(v1, 0.f); v1 *= v1;
                    __nv_bfloat16 h0, l0, h1, l1;
                    split_bf(v0, h0, l0);
                    split_bf(v1, h1, l1);
                    __nv_bfloat162 hh, ll;
                    hh.x = h0; hh.y = h1;
                    ll.x = l0; ll.y = l1;
                    const size_t o = (size_t)(r0 + 8 * half) * N + cc;
                    *(__nv_bfloat162*)(Chi + o) = hh;
                    *(__nv_bfloat162*)(Clo + o) = ll;
                }
            }
        }
    }
}

// ---------------- causal flash attention (fp32, bf16-split output) ----------
#define FLASH_SMEM ((3 * 64 * 128 + 64 * 68) * 4)

__global__ __launch_bounds__(256) void flash_kernel(
    const float* __restrict__ gq, const float* __restrict__ gk,
    const float* __restrict__ gv, __nv_bfloat16* __restrict__ ohi,
    __nv_bfloat16* __restrict__ olo)
{
    extern __shared__ float sm[];
    float* Qs = sm;
    float* Ks = sm + 64 * 128;
    float* Vs = sm + 2 * 64 * 128;
    float* Ps = sm + 3 * 64 * 128;

    const int tid = threadIdx.x;
    const int tx = tid & 15;
    const int ty = tid >> 4;
    const int qt = blockIdx.x;
    const int h = blockIdx.y;
    const int b = blockIdx.z;
    const int kvh = h & 3;

    const float* qbase = gq + (((size_t)(b * QC_ + h)) * S_ + qt * 64) * HD_;
    const float* kbase = gk + ((size_t)(b * KVC_ + kvh)) * S_ * HD_;
    const float* vbase = gv + ((size_t)(b * KVC_ + kvh)) * S_ * HD_;

#pragma unroll
    for (int i = 0; i < 8; i++) {
        const int off = i * 1024 + tid * 4;
        const int r = off >> 7;
        const int d4 = (off & 127) >> 2;
        *(float4*)(Qs + r * 128 + ((d4 ^ (r & 31)) << 2)) = *(const float4*)(qbase + off);
    }

    float o[4][8];
    float m[4], l[4];
#pragma unroll
    for (int i = 0; i < 4; i++) {
        m[i] = -1e30f; l[i] = 0.f;
#pragma unroll
        for (int j = 0; j < 8; j++) o[i][j] = 0.f;
    }

    const int rowq[4] = { ty, ty + 16, ty + 32, ty + 48 };
    const int rowk[4] = { tx, tx + 16, tx + 32, tx + 48 };

    for (int kt = 0; kt <= qt; kt++) {
        __syncthreads();
#pragma unroll
        for (int i = 0; i < 8; i++) {
            const int off = i * 1024 + tid * 4;
            const int r = off >> 7;
            const int d4 = (off & 127) >> 2;
            const int sw = r * 128 + ((d4 ^ (r & 31)) << 2);
            *(float4*)(Ks + sw) = *(const float4*)(kbase + (size_t)kt * 64 * HD_ + off);
            *(float4*)(Vs + sw) = *(const float4*)(vbase + (size_t)kt * 64 * HD_ + off);
        }
        __syncthreads();

        float s[4][4] = {};
#pragma unroll 4
        for (int d4 = 0; d4 < 32; d4++) {
            float4 q4[4], k4[4];
#pragma unroll
            for (int i = 0; i < 4; i++)
                q4[i] = *(const float4*)(Qs + rowq[i] * 128 + ((d4 ^ (rowq[i] & 31)) << 2));
#pragma unroll
            for (int j = 0; j < 4; j++)
                k4[j] = *(const float4*)(Ks + rowk[j] * 128 + ((d4 ^ (rowk[j] & 31)) << 2));
#pragma unroll
            for (int i = 0; i < 4; i++)
#pragma unroll
                for (int j = 0; j < 4; j++)
                    s[i][j] += q4[i].x * k4[j].x + q4[i].y * k4[j].y
                             + q4[i].z * k4[j].z + q4[i].w * k4[j].w;
        }

        if (kt == qt) {
#pragma unroll
            for (int i = 0; i < 4; i++)
#pragma unroll
                for (int j = 0; j < 4; j++)
                    if (rowk[j] > rowq[i]) s[i][j] -= 1e9f;
        }

#pragma unroll
        for (int i = 0; i < 4; i++) {
            float mx = fmaxf(fmaxf(s[i][0], s[i][1]), fmaxf(s[i][2], s[i][3]));
#pragma unroll
            for (int sh = 1; sh < 16; sh <<= 1)
                mx = fmaxf(mx, __shfl_xor_sync(0xffffffffu, mx, sh));
            const float mn = fmaxf(m[i], mx);
            const float sc = __expf(m[i] - mn);
            m[i] = mn;
            float rs = 0.f;
#pragma unroll
            for (int j = 0; j < 4; j++) {
                const float p = __expf(s[i][j] - mn);
                s[i][j] = p;
                rs += p;
            }
#pragma unroll
            for (int sh = 1; sh < 16; sh <<= 1)
                rs += __shfl_xor_sync(0xffffffffu, rs, sh);
            l[i] = l[i] * sc + rs;
#pragma unroll
            for (int j = 0; j < 8; j++) o[i][j] *= sc;
#pragma unroll
            for (int j = 0; j < 4; j++)
                Ps[rowq[i] * 68 + rowk[j]] = s[i][j];
        }
        __syncthreads();

#pragma unroll 2
        for (int jk = 0; jk < 64; jk++) {
            const float4 va = *(const float4*)(Vs + jk * 128 + ((tx ^ (jk & 31)) << 2));
            const float4 vb = *(const float4*)(Vs + jk * 128 + (((tx + 16) ^ (jk & 31)) << 2));
#pragma unroll
            for (int i = 0; i < 4; i++) {
                const float p = Ps[rowq[i] * 68 + jk];
                o[i][0] += p * va.x; o[i][1] += p * va.y;
                o[i][2] += p * va.z; o[i][3] += p * va.w;
                o[i][4] += p * vb.x; o[i][5] += p * vb.y;
                o[i][6] += p * vb.z; o[i][7] += p * vb.w;
            }
        }
    }

#pragma unroll
    for (int i = 0; i < 4; i++) {
        const float inv = 1.f / l[i];
        const int srow = qt * 64 + rowq[i];
        const size_t base = ((size_t)b * S_ + srow) * D_ + h * HD_;
#pragma unroll
        for (int j = 0; j < 8; j++) {
            const float v0 = o[i][j] * inv;
            const size_t off = base + ((j < 4) ? (4 * tx + j) : (64 + 4 * tx + j - 4));
            __nv_bfloat16 hh, ll;
            split_bf(v0, hh, ll);
            ohi[off] = hh;
            olo[off] = ll;
        }
    }
}

// ---------------- launcher ----------------
extern "C" void kernel_launch(void* const* d_in, const int* in_sizes, int n_in,
                              void* d_out, int out_size)
{
    (void)in_sizes; (void)n_in; (void)out_size;
    const float* x    = (const float*)d_in[0];
    const float* rsin = (const float*)d_in[2];
    const float* rcos = (const float*)d_in[3];
    const float* wqkv = (const float*)d_in[4];
    const float* wo   = (const float*)d_in[5];
    const float* n1   = (const float*)d_in[6];
    const float* n2   = (const float*)d_in[7];
    const float* wk   = (const float*)d_in[8];
    const float* wv   = (const float*)d_in[9];
    float* out = (float*)d_out;

    float *p_qkv, *p_q, *p_k, *p_v, *p_x1;
    __nv_bfloat16 *p_xn_hi, *p_xn_lo, *p_at_hi, *p_at_lo, *p_h_hi, *p_h_lo;
    __nv_bfloat16 *p_wqkv_hi, *p_wqkv_lo, *p_wo_hi, *p_wo_lo, *p_wk_hi, *p_wk_lo, *p_wv_hi, *p_wv_lo;
    cudaGetSymbolAddress((void**)&p_qkv, g_qkv);
    cudaGetSymbolAddress((void**)&p_q, g_q);
    cudaGetSymbolAddress((void**)&p_k, g_k);
    cudaGetSymbolAddress((void**)&p_v, g_v);
    cudaGetSymbolAddress((void**)&p_x1, g_x1);
    cudaGetSymbolAddress((void**)&p_xn_hi, g_xn_hi);
    cudaGetSymbolAddress((void**)&p_xn_lo, g_xn_lo);
    cudaGetSymbolAddress((void**)&p_at_hi, g_at_hi);
    cudaGetSymbolAddress((void**)&p_at_lo, g_at_lo);
    cudaGetSymbolAddress((void**)&p_h_hi, g_h_hi);
    cudaGetSymbolAddress((void**)&p_h_lo, g_h_lo);
    cudaGetSymbolAddress((void**)&p_wqkv_hi, g_wqkv_hi);
    cudaGetSymbolAddress((void**)&p_wqkv_lo, g_wqkv_lo);
    cudaGetSymbolAddress((void**)&p_wo_hi, g_wo_hi);
    cudaGetSymbolAddress((void**)&p_wo_lo, g_wo_lo);
    cudaGetSymbolAddress((void**)&p_wk_hi, g_wk_hi);
    cudaGetSymbolAddress((void**)&p_wk_lo, g_wk_lo);
    cudaGetSymbolAddress((void**)&p_wv_hi, g_wv_hi);
    cudaGetSymbolAddress((void**)&p_wv_lo, g_wv_lo);

    cudaFuncSetAttribute(flash_kernel, cudaFuncAttributeMaxDynamicSharedMemorySize, FLASH_SMEM);
    cudaFuncSetAttribute(mma_gemm<0>, cudaFuncAttributeMaxDynamicSharedMemorySize, GEMM_SMEM);
    cudaFuncSetAttribute(mma_gemm<1>, cudaFuncAttributeMaxDynamicSharedMemorySize, GEMM_SMEM);
    cudaFuncSetAttribute(mma_gemm<2>, cudaFuncAttributeMaxDynamicSharedMemorySize, GEMM_SMEM);

    const dim3 tb(32, 8);
    wsplit_kernel<<<dim3(QKVN / 32, D_ / 32), tb>>>(wqkv, p_wqkv_hi, p_wqkv_lo, D_, QKVN);
    wsplit_kernel<<<dim3(D_ / 32, D_ / 32), tb>>>(wo, p_wo_hi, p_wo_lo, D_, D_);
    wsplit_kernel<<<dim3(FF_ / 32, D_ / 32), tb>>>(wk, p_wk_hi, p_wk_lo, D_, FF_);
    wsplit_kernel<<<dim3(D_ / 32, FF_ / 32), tb>>>(wv, p_wv_hi, p_wv_lo, FF_, D_);

    // x1 = x + attn(rmsnorm(x))
    rmsnorm_bf_kernel<<<M_, 256>>>(x, n1, p_xn_hi, p_xn_lo);
    mma_gemm<0><<<dim3(QKVN / 128, M_ / 128), 256, GEMM_SMEM>>>(
        p_xn_hi, p_xn_lo, p_wqkv_hi, p_wqkv_lo, nullptr, p_qkv, nullptr, nullptr, QKVN, D_);
    rope_kernel<<<M_, 256>>>(p_qkv, rsin, rcos, p_q, p_k, p_v);
    flash_kernel<<<dim3(S_ / 64, QC_, B_), 256, FLASH_SMEM>>>(p_q, p_k, p_v, p_at_hi, p_at_lo);
    mma_gemm<1><<<dim3(D_ / 128, M_ / 128), 256, GEMM_SMEM>>>(
        p_at_hi, p_at_lo, p_wo_hi, p_wo_lo, x, p_x1, nullptr, nullptr, D_, D_);

    // out = x1 + ffn(rmsnorm(x1))
    rmsnorm_bf_kernel<<<M_, 256>>>(p_x1, n2, p_xn_hi, p_xn_lo);
    mma_gemm<2><<<dim3(FF_ / 128, M_ / 128), 256, GEMM_SMEM>>>(
        p_xn_hi, p_xn_lo, p_wk_hi, p_wk_lo, nullptr, nullptr, p_h_hi, p_h_lo, FF_, D_);
    mma_gemm<1><<<dim3(D_ / 128, M_ / 128), 256, GEMM_SMEM>>>(
        p_h_hi, p_h_lo, p_wv_hi, p_wv_lo, p_x1, out, nullptr, nullptr, D_, FF_);
}

// round 4
// speedup vs baseline: 2.5882x; 1.1812x over previous
#include <cuda_runtime.h>
#include <cuda_bf16.h>
#include <cstdint>
#include <cstddef>

#define B_   2
#define S_   2048
#define D_   2048
#define QC_  16
#define KVC_ 4
#define HD_  128
#define FF_  8192
#define M_   (B_ * S_)             // 4096
#define QKVN (D_ + 2 * KVC_ * HD_) // 3072

// ---------------- scratch ----------------
__device__ float g_qkv [(size_t)M_ * QKVN];
__device__ float g_x1  [(size_t)M_ * D_];
__device__ __nv_bfloat16 g_qh [(size_t)B_ * QC_  * S_ * HD_];
__device__ __nv_bfloat16 g_ql [(size_t)B_ * QC_  * S_ * HD_];
__device__ __nv_bfloat16 g_kh [(size_t)B_ * KVC_ * S_ * HD_];
__device__ __nv_bfloat16 g_kl [(size_t)B_ * KVC_ * S_ * HD_];
__device__ __nv_bfloat16 g_vh [(size_t)B_ * KVC_ * S_ * HD_];
__device__ __nv_bfloat16 g_vl [(size_t)B_ * KVC_ * S_ * HD_];
__device__ __nv_bfloat16 g_xn_hi [(size_t)M_ * D_];
__device__ __nv_bfloat16 g_xn_lo [(size_t)M_ * D_];
__device__ __nv_bfloat16 g_at_hi [(size_t)M_ * D_];
__device__ __nv_bfloat16 g_at_lo [(size_t)M_ * D_];
__device__ __nv_bfloat16 g_h_hi  [(size_t)M_ * FF_];
__device__ __nv_bfloat16 g_h_lo  [(size_t)M_ * FF_];
__device__ __nv_bfloat16 g_wqkv_hi[(size_t)QKVN * D_];
__device__ __nv_bfloat16 g_wqkv_lo[(size_t)QKVN * D_];
__device__ __nv_bfloat16 g_wo_hi [(size_t)D_ * D_];
__device__ __nv_bfloat16 g_wo_lo [(size_t)D_ * D_];
__device__ __nv_bfloat16 g_wk_hi [(size_t)FF_ * D_];
__device__ __nv_bfloat16 g_wk_lo [(size_t)FF_ * D_];
__device__ __nv_bfloat16 g_wv_hi [(size_t)D_ * FF_];
__device__ __nv_bfloat16 g_wv_lo [(size_t)D_ * FF_];

// ---------------- helpers ----------------
__device__ __forceinline__ uint32_t smem_u32(const void* p) {
    uint32_t a;
    asm("{ .reg .u64 t; cvta.to.shared.u64 t, %1; cvt.u32.u64 %0, t; }" : "=r"(a) : "l"(p));
    return a;
}
__device__ __forceinline__ void split_bf(float v, __nv_bfloat16& h, __nv_bfloat16& l) {
    h = __float2bfloat16(v);
    l = __float2bfloat16(v - __bfloat162float(h));
}
__device__ __forceinline__ uint32_t packbf(float lo, float hi) {
    uint32_t r;
    asm("cvt.rn.bf16x2.f32 %0, %1, %2;" : "=r"(r) : "f"(hi), "f"(lo));
    return r;
}
// split two floats -> (hi bf16x2, lo bf16x2)
__device__ __forceinline__ void split2(float x, float y, uint32_t& hi, uint32_t& lo) {
    const float hx = __bfloat162float(__float2bfloat16(x));
    const float hy = __bfloat162float(__float2bfloat16(y));
    hi = packbf(hx, hy);
    lo = packbf(x - hx, y - hy);
}
__device__ __forceinline__ float ex2(float x) {
    float y;
    asm("ex2.approx.f32 %0, %1;" : "=f"(y) : "f"(x));
    return y;
}

#define SW(o) (((uint32_t)(o)) ^ ((((uint32_t)(o)) >> 3) & 0x70u))

__device__ __forceinline__ void ldsm4(uint32_t* r, uint32_t addr) {
    asm volatile("ldmatrix.sync.aligned.m8n8.x4.shared.b16 {%0,%1,%2,%3},[%4];"
                 : "=r"(r[0]), "=r"(r[1]), "=r"(r[2]), "=r"(r[3]) : "r"(addr));
}
__device__ __forceinline__ void ldsm4t(uint32_t* r, uint32_t addr) {
    asm volatile("ldmatrix.sync.aligned.m8n8.x4.trans.shared.b16 {%0,%1,%2,%3},[%4];"
                 : "=r"(r[0]), "=r"(r[1]), "=r"(r[2]), "=r"(r[3]) : "r"(addr));
}
__device__ __forceinline__ void hmma(float* c, const uint32_t* a, const uint32_t* b) {
    asm volatile("mma.sync.aligned.m16n8k16.row.col.f32.bf16.bf16.f32 "
                 "{%0,%1,%2,%3},{%4,%5,%6,%7},{%8,%9},{%0,%1,%2,%3};"
                 : "+f"(c[0]), "+f"(c[1]), "+f"(c[2]), "+f"(c[3])
                 : "r"(a[0]), "r"(a[1]), "r"(a[2]), "r"(a[3]), "r"(b[0]), "r"(b[1]));
}
__device__ __forceinline__ void cpa(uint32_t dst, const void* src) {
    asm volatile("cp.async.cg.shared.global [%0],[%1],16;" :: "r"(dst), "l"(src));
}

// ---------------- RMSNorm -> bf16 hi/lo ----------------
__global__ __launch_bounds__(256) void rmsnorm_bf_kernel(
    const float* __restrict__ x, const float* __restrict__ w,
    __nv_bfloat16* __restrict__ ohi, __nv_bfloat16* __restrict__ olo)
{
    const int row = blockIdx.x;
    const int tid = threadIdx.x;
    const float4* xr = (const float4*)(x + (size_t)row * D_);
    float4 vals[2];
    float ss = 0.f;
#pragma unroll
    for (int i = 0; i < 2; i++) {
        float4 v = xr[tid + 256 * i];
        vals[i] = v;
        ss += v.x * v.x + v.y * v.y + v.z * v.z + v.w * v.w;
    }
#pragma unroll
    for (int sh = 16; sh > 0; sh >>= 1) ss += __shfl_xor_sync(0xffffffffu, ss, sh);
    __shared__ float red[8];
    if ((tid & 31) == 0) red[tid >> 5] = ss;
    __syncthreads();
    float tot = 0.f;
#pragma unroll
    for (int i = 0; i < 8; i++) tot += red[i];
    const float rs = rsqrtf(tot * (1.f / (float)D_) + 1e-5f);
    const float4* w4 = (const float4*)w;
#pragma unroll
    for (int i = 0; i < 2; i++) {
        float4 v = vals[i], ww = w4[tid + 256 * i];
        float r0 = v.x * rs * ww.x, r1 = v.y * rs * ww.y;
        float r2 = v.z * rs * ww.z, r3 = v.w * rs * ww.w;
        const size_t base = (size_t)row * D_ + (tid + 256 * i) * 4;
        uint32_t h0, l0, h1, l1;
        split2(r0, r1, h0, l0);
        split2(r2, r3, h1, l1);
        *(uint32_t*)(ohi + base) = h0;
        *(uint32_t*)(ohi + base + 2) = h1;
        *(uint32_t*)(olo + base) = l0;
        *(uint32_t*)(olo + base + 2) = l1;
    }
}

// ---------------- weight transpose + split ----------------
__global__ __launch_bounds__(256) void wsplit_kernel(
    const float* __restrict__ W, __nv_bfloat16* __restrict__ hi,
    __nv_bfloat16* __restrict__ lo, int K, int N)
{
    __shared__ float t[32][33];
    const int tx = threadIdx.x, ty = threadIdx.y;
    const int n0 = blockIdx.x * 32, k0 = blockIdx.y * 32;
#pragma unroll
    for (int j = 0; j < 4; j++)
        t[ty + 8 * j][tx] = W[(size_t)(k0 + ty + 8 * j) * N + n0 + tx];
    __syncthreads();
#pragma unroll
    for (int j = 0; j < 4; j++) {
        const float v = t[tx][ty + 8 * j];
        __nv_bfloat16 h, l;
        split_bf(v, h, l);
        const size_t o = (size_t)(n0 + ty + 8 * j) * K + k0 + tx;
        hi[o] = h;
        lo[o] = l;
    }
}

// ---------------- RoPE -> bf16 hi/lo q/k/v ----------------
__global__ __launch_bounds__(256) void rope_kernel(
    const float* __restrict__ qkv, const float* __restrict__ rsin,
    const float* __restrict__ rcos,
    __nv_bfloat16* __restrict__ qh, __nv_bfloat16* __restrict__ ql,
    __nv_bfloat16* __restrict__ kh, __nv_bfloat16* __restrict__ kl,
    __nv_bfloat16* __restrict__ vh, __nv_bfloat16* __restrict__ vl)
{
    const int t = blockIdx.x;
    const int b = t / S_;
    const int s = t % S_;
    const int tid = threadIdx.x;
    const float* row = qkv + (size_t)t * QKVN;
    const float* sinr = rsin + (size_t)s * HD_;
    const float* cosr = rcos + (size_t)s * HD_;
    // q
    for (int p = tid; p < 1024; p += 256) {
        const int h = p >> 6, pp = p & 63;
        const float x0 = row[2 * p], x1 = row[2 * p + 1];
        const float sn = sinr[2 * pp], cs = cosr[2 * pp];
        const float q0 = x0 * cs - x1 * sn;
        const float q1 = x1 * cs + x0 * sn;
        const size_t o = (((size_t)(b * QC_ + h)) * S_ + s) * HD_ + 2 * pp;
        uint32_t hp, lp;
        split2(q0, q1, hp, lp);
        *(uint32_t*)(qh + o) = hp;
        *(uint32_t*)(ql + o) = lp;
    }
    // k : pre-scale by HD^-0.5 * log2(e)  (log2-domain softmax)
    const float ks = 0.08838834764831845f * 1.4426950408889634f;
    for (int p = tid; p < 256; p += 256) {
        const int h = p >> 6, pp = p & 63;
        const float x0 = row[D_ + 2 * p], x1 = row[D_ + 2 * p + 1];
        const float sn = sinr[2 * pp], cs = cosr[2 * pp];
        const float k0 = (x0 * cs - x1 * sn) * ks;
        const float k1 = (x1 * cs + x0 * sn) * ks;
        const size_t o = (((size_t)(b * KVC_ + h)) * S_ + s) * HD_ + 2 * pp;
        uint32_t hp, lp;
        split2(k0, k1, hp, lp);
        *(uint32_t*)(kh + o) = hp;
        *(uint32_t*)(kl + o) = lp;
    }
    // v
    for (int e = tid; e < 256; e += 256) {
        const int h = e >> 6, d = (e & 63) * 2;
        const float v0 = row[D_ + 512 + e * 2];
        const float v1 = row[D_ + 512 + e * 2 + 1];
        const size_t o = (((size_t)(b * KVC_ + h)) * S_ + s) * HD_ + d;
        uint32_t hp, lp;
        split2(v0, v1, hp, lp);
        *(uint32_t*)(vh + o) = hp;
        *(uint32_t*)(vl + o) = lp;
    }
}

// ---------------- HMMA GEMM v2: CTA 128x256, warp 64x64, 3xBF16 ----------------
#define PIPE 2
#define STG  98304
#define OF_AH 0
#define OF_AL 16384
#define OF_BH 32768
#define OF_BL 65536
#define GEMM_SMEM (PIPE * STG)

template <int EPI>
__global__ __launch_bounds__(256) void mma_gemm(
    const __nv_bfloat16* __restrict__ Ahi, const __nv_bfloat16* __restrict__ Alo,
    const __nv_bfloat16* __restrict__ Bhi, const __nv_bfloat16* __restrict__ Blo,
    const float* __restrict__ R, float* __restrict__ Cf,
    __nv_bfloat16* __restrict__ Chi, __nv_bfloat16* __restrict__ Clo,
    int N, int K)
{
    extern __shared__ char smem[];
    const uint32_t sb = smem_u32(smem);
    const int tid = threadIdx.x;
    const int wid = tid >> 5, lane = tid & 31;
    const int wm = wid & 1, wn = wid >> 1;
    const int bm = blockIdx.y * 128, bn = blockIdx.x * 256;
    const int NC = K >> 6;

    float acc[4][8][4];
#pragma unroll
    for (int i = 0; i < 4; i++)
#pragma unroll
        for (int j = 0; j < 8; j++)
#pragma unroll
            for (int q = 0; q < 4; q++) acc[i][j][q] = 0.f;

    auto issue = [&](int c) {
        if (c < NC) {
            const int kc = c << 6;
            const uint32_t st = sb + (uint32_t)(c & 1) * STG;
            const char* pa_hi = (const char*)(Ahi + (size_t)bm * K + kc);
            const char* pa_lo = (const char*)(Alo + (size_t)bm * K + kc);
            const char* pb_hi = (const char*)(Bhi + (size_t)bn * K + kc);
            const char* pb_lo = (const char*)(Blo + (size_t)bn * K + kc);
#pragma unroll
            for (int i = 0; i < 4; i++) {
                const int idx = tid + 256 * i;
                const int r = idx >> 3;
                const uint32_t ch = (idx & 7) << 4;
                const uint32_t so = SW(r * 128 + ch);
                const size_t go = (size_t)r * (K * 2) + ch;
                cpa(st + OF_AH + so, pa_hi + go);
                cpa(st + OF_AL + so, pa_lo + go);
            }
#pragma unroll
            for (int i = 0; i < 8; i++) {
                const int idx = tid + 256 * i;
                const int r = idx >> 3;
                const uint32_t ch = (idx & 7) << 4;
                const uint32_t so = SW(r * 128 + ch);
                const size_t go = (size_t)r * (K * 2) + ch;
                cpa(st + OF_BH + so, pb_hi + go);
                cpa(st + OF_BL + so, pb_lo + go);
            }
        }
        asm volatile("cp.async.commit_group;");
    };

    issue(0);
    issue(1);

    const uint32_t arow = (uint32_t)(wm * 64 + (lane & 15));
    const uint32_t brow = (uint32_t)(wn * 64 + (lane & 15));
    const uint32_t khalf = ((uint32_t)lane >> 4) << 4;

    for (int c = 0; c < NC; c++) {
        asm volatile("cp.async.wait_group 1;" ::: "memory");
        __syncthreads();
        const uint32_t st = sb + (uint32_t)(c & 1) * STG;
#pragma unroll
        for (int ks = 0; ks < 4; ks++) {
            const uint32_t col = (uint32_t)ks * 32 + khalf;
            uint32_t ah[4][4], al[4][4];
#pragma unroll
            for (int mt = 0; mt < 4; mt++) {
                const uint32_t off = SW((arow + mt * 16) * 128 + col);
                ldsm4(ah[mt], st + OF_AH + off);
                ldsm4(al[mt], st + OF_AL + off);
            }
#pragma unroll
            for (int ntp = 0; ntp < 4; ntp++) {
                const uint32_t off = SW((brow + ntp * 16) * 128 + col);
                uint32_t rh[4], rl[4];
                ldsm4(rh, st + OF_BH + off);
                ldsm4(rl, st + OF_BL + off);
                uint32_t b0h[2] = { rh[0], rh[2] }, b1h[2] = { rh[1], rh[3] };
                uint32_t b0l[2] = { rl[0], rl[2] }, b1l[2] = { rl[1], rl[3] };
#pragma unroll
                for (int mt = 0; mt < 4; mt++) {
                    hmma(acc[mt][2 * ntp],     ah[mt], b0h);
                    hmma(acc[mt][2 * ntp],     al[mt], b0h);
                    hmma(acc[mt][2 * ntp],     ah[mt], b0l);
                    hmma(acc[mt][2 * ntp + 1], ah[mt], b1h);
                    hmma(acc[mt][2 * ntp + 1], al[mt], b1h);
                    hmma(acc[mt][2 * ntp + 1], ah[mt], b1l);
                }
            }
        }
        __syncthreads();
        issue(c + 2);
    }

    // epilogue
    const int row0 = bm + wm * 64 + (lane >> 2);
    const int col0 = bn + wn * 64 + ((lane & 3) << 1);
#pragma unroll
    for (int mt = 0; mt < 4; mt++) {
#pragma unroll
        for (int nt = 0; nt < 8; nt++) {
            const int r0 = row0 + mt * 16;
            const int cc = col0 + nt * 8;
            if (EPI <= 1) {
                float2 v0 = make_float2(acc[mt][nt][0], acc[mt][nt][1]);
                float2 v1 = make_float2(acc[mt][nt][2], acc[mt][nt][3]);
                if (EPI == 1) {
                    const float2 ra = *(const float2*)(R + (size_t)r0 * N + cc);
                    const float2 rb = *(const float2*)(R + (size_t)(r0 + 8) * N + cc);
                    v0.x += ra.x; v0.y += ra.y;
                    v1.x += rb.x; v1.y += rb.y;
                }
                *(float2*)(Cf + (size_t)r0 * N + cc) = v0;
                *(float2*)(Cf + (size_t)(r0 + 8) * N + cc) = v1;
            } else {
#pragma unroll
                for (int half = 0; half < 2; half++) {
                    float v0 = acc[mt][nt][2 * half + 0];
                    float v1 = acc[mt][nt][2 * half + 1];
                    v0 = fmaxf(v0, 0.f); v0 *= v0;
                    v1 = fmaxf(v1, 0.f); v1 *= v1;
                    uint32_t hp, lp;
                    split2(v0, v1, hp, lp);
                    const size_t o = (size_t)(r0 + 8 * half) * N + cc;
                    *(uint32_t*)(Chi + o) = hp;
                    *(uint32_t*)(Clo + o) = lp;
                }
            }
        }
    }
}

// ---------------- HMMA flash attention ----------------
// CTA: 64 q-rows, 4 warps (warp = m16), Bc = 64 keys, HD = 128.
// log2-domain softmax (K pre-scaled by log2e), 3xBF16 on both QK^T and PV.
#define FL_QH 0
#define FL_QL 16384
#define FL_ST(s) (32768 + (s) * 65536)
#define FL_KH 0
#define FL_KL 16384
#define FL_VH 32768
#define FL_VL 49152
#define FLASH_SMEM (32768 + 2 * 65536)

// smem tile offset: [2 hd-halves][64 rows][128B], swizzled
__device__ __forceinline__ uint32_t floff(uint32_t r, uint32_t hb) {
    return (hb >> 7) * 8192 + r * 128 + ((hb & 127) ^ ((r & 7) << 4));
}

__global__ __launch_bounds__(128) void flash_kernel(
    const __nv_bfloat16* __restrict__ qh, const __nv_bfloat16* __restrict__ ql,
    const __nv_bfloat16* __restrict__ kh, const __nv_bfloat16* __restrict__ kl,
    const __nv_bfloat16* __restrict__ vh, const __nv_bfloat16* __restrict__ vl,
    __nv_bfloat16* __restrict__ ohi, __nv_bfloat16* __restrict__ olo)
{
    extern __shared__ char smem[];
    const uint32_t sb = smem_u32(smem);
    const int tid = threadIdx.x;
    const int w = tid >> 5, lane = tid & 31;
    const int qt = (int)(gridDim.x - 1 - blockIdx.x);   // big tiles first
    const int h = blockIdx.y;
    const int b = blockIdx.z;
    const int kvh = h & 3;

    const __nv_bfloat16* qbh = qh + (((size_t)(b * QC_ + h)) * S_ + qt * 64) * HD_;
    const __nv_bfloat16* qbl = ql + (((size_t)(b * QC_ + h)) * S_ + qt * 64) * HD_;
    const size_t kvbase = ((size_t)(b * KVC_ + kvh)) * S_ * HD_;

    auto ldtile = [&](uint32_t dst, const __nv_bfloat16* src) {
#pragma unroll
        for (int i = 0; i < 8; i++) {
            const int idx = tid + 128 * i;
            const uint32_t r = (uint32_t)idx >> 4;
            const uint32_t hb = ((uint32_t)idx & 15) << 4;
            cpa(dst + floff(r, hb), (const char*)src + (size_t)r * 256 + hb);
        }
    };
    auto issue = [&](int kt) {
        if (kt <= qt) {
            const uint32_t st = sb + FL_ST(kt & 1);
            const __nv_bfloat16* kbh = kh + kvbase + (size_t)kt * 64 * HD_;
            const __nv_bfloat16* kbl = kl + kvbase + (size_t)kt * 64 * HD_;
            const __nv_bfloat16* vbh = vh + kvbase + (size_t)kt * 64 * HD_;
            const __nv_bfloat16* vbl = vl + kvbase + (size_t)kt * 64 * HD_;
            ldtile(st + FL_KH, kbh);
            ldtile(st + FL_KL, kbl);
            ldtile(st + FL_VH, vbh);
            ldtile(st + FL_VL, vbl);
        }
        asm volatile("cp.async.commit_group;");
    };

    // group 0: Q + KV stage 0 ; group 1: KV stage 1
    ldtile(sb + FL_QH, qbh);
    ldtile(sb + FL_QL, qbl);
    issue(0);
    issue(1);

    float o[16][4];
#pragma unroll
    for (int i = 0; i < 16; i++)
#pragma unroll
        for (int j = 0; j < 4; j++) o[i][j] = 0.f;
    float m_l = -1e30f, m_h = -1e30f, l_l = 0.f, l_h = 0.f;

    const uint32_t arow = (uint32_t)(w * 16 + (lane & 15));
    const uint32_t khalf = ((uint32_t)lane >> 4) << 4;
    const int rl = lane >> 2;              // row (low) within warp m16
    const int cq = (lane & 3) << 1;        // col pair base within n8 tile

    for (int kt = 0; kt <= qt; kt++) {
        asm volatile("cp.async.wait_group 1;" ::: "memory");
        __syncthreads();
        const uint32_t st = sb + FL_ST(kt & 1);

        // ---- S = Q K^T (3x split), log2-domain logits ----
        float sacc[8][4];
#pragma unroll
        for (int i = 0; i < 8; i++)
#pragma unroll
            for (int j = 0; j < 4; j++) sacc[i][j] = 0.f;

#pragma unroll
        for (int ks = 0; ks < 8; ks++) {
            const uint32_t hb = (uint32_t)ks * 32 + khalf;
            uint32_t aqh[4], aql[4];
            ldsm4(aqh, sb + FL_QH + floff(arow, hb));
            ldsm4(aql, sb + FL_QL + floff(arow, hb));
#pragma unroll
            for (int ntp = 0; ntp < 4; ntp++) {
                const uint32_t krow = (uint32_t)(ntp * 16) + (lane & 15);
                uint32_t rh[4], rlw[4];
                ldsm4(rh, st + FL_KH + floff(krow, hb));
                ldsm4(rlw, st + FL_KL + floff(krow, hb));
                uint32_t b0h[2] = { rh[0], rh[2] }, b1h[2] = { rh[1], rh[3] };
                uint32_t b0l[2] = { rlw[0], rlw[2] }, b1l[2] = { rlw[1], rlw[3] };
                hmma(sacc[2 * ntp], aqh, b0h);
                hmma(sacc[2 * ntp], aql, b0h);
                hmma(sacc[2 * ntp], aqh, b0l);
                hmma(sacc[2 * ntp + 1], aqh, b1h);
                hmma(sacc[2 * ntp + 1], aql, b1h);
                hmma(sacc[2 * ntp + 1], aqh, b1l);
            }
        }

        // ---- causal mask on diagonal tile ----
        if (kt == qt) {
            const int rowl = w * 16 + rl;
            const int rowh = rowl + 8;
#pragma unroll
            for (int nt = 0; nt < 8; nt++) {
                const int c0 = nt * 8 + cq, c1 = c0 + 1;
                if (c0 > rowl) sacc[nt][0] = -1e30f;
                if (c1 > rowl) sacc[nt][1] = -1e30f;
                if (c0 > rowh) sacc[nt][2] = -1e30f;
                if (c1 > rowh) sacc[nt][3] = -1e30f;
            }
        }

        // ---- online softmax (base-2) ----
        float mx_l = -1e30f, mx_h = -1e30f;
#pragma unroll
        for (int nt = 0; nt < 8; nt++) {
            mx_l = fmaxf(mx_l, fmaxf(sacc[nt][0], sacc[nt][1]));
            mx_h = fmaxf(mx_h, fmaxf(sacc[nt][2], sacc[nt][3]));
        }
#pragma unroll
        for (int sh = 1; sh < 4; sh <<= 1) {
            mx_l = fmaxf(mx_l, __shfl_xor_sync(0xffffffffu, mx_l, sh));
            mx_h = fmaxf(mx_h, __shfl_xor_sync(0xffffffffu, mx_h, sh));
        }
        const float mn_l = fmaxf(m_l, mx_l);
        const float mn_h = fmaxf(m_h, mx_h);
        const float sc_l = ex2(m_l - mn_l);
        const float sc_h = ex2(m_h - mn_h);
        m_l = mn_l;
        m_h = mn_h;

        float sum_l = 0.f, sum_h = 0.f;
#pragma unroll
        for (int nt = 0; nt < 8; nt++) {
            sacc[nt][0] = ex2(sacc[nt][0] - mn_l);
            sacc[nt][1] = ex2(sacc[nt][1] - mn_l);
            sacc[nt][2] = ex2(sacc[nt][2] - mn_h);
            sacc[nt][3] = ex2(sacc[nt][3] - mn_h);
            sum_l += sacc[nt][0] + sacc[nt][1];
            sum_h += sacc[nt][2] + sacc[nt][3];
        }
#pragma unroll
        for (int sh = 1; sh < 4; sh <<= 1) {
            sum_l += __shfl_xor_sync(0xffffffffu, sum_l, sh);
            sum_h += __shfl_xor_sync(0xffffffffu, sum_h, sh);
        }
        l_l = l_l * sc_l + sum_l;
        l_h = l_h * sc_h + sum_h;
#pragma unroll
        for (int i = 0; i < 16; i++) {
            o[i][0] *= sc_l; o[i][1] *= sc_l;
            o[i][2] *= sc_h; o[i][3] *= sc_h;
        }

        // ---- P frags (split) ----
        uint32_t ph[4][4], pl[4][4];
#pragma unroll
        for (int kf = 0; kf < 4; kf++) {
            split2(sacc[2 * kf][0], sacc[2 * kf][1], ph[kf][0], pl[kf][0]);
            split2(sacc[2 * kf][2], sacc[2 * kf][3], ph[kf][1], pl[kf][1]);
            split2(sacc[2 * kf + 1][0], sacc[2 * kf + 1][1], ph[kf][2], pl[kf][2]);
            split2(sacc[2 * kf + 1][2], sacc[2 * kf + 1][3], ph[kf][3], pl[kf][3]);
        }

        // ---- O += P V (3x split) ----
#pragma unroll
        for (int kf = 0; kf < 4; kf++) {
            const uint32_t vrow = (uint32_t)(kf * 16) + (lane & 7) + (((uint32_t)lane >> 3) & 1) * 8;
#pragma unroll
            for (int np = 0; np < 8; np++) {
                const uint32_t hb = (uint32_t)np * 32 + khalf;
                uint32_t rvh[4], rvl[4];
                ldsm4t(rvh, st + FL_VH + floff(vrow, hb));
                ldsm4t(rvl, st + FL_VL + floff(vrow, hb));
                uint32_t b0h[2] = { rvh[0], rvh[1] }, b1h[2] = { rvh[2], rvh[3] };
                uint32_t b0l[2] = { rvl[0], rvl[1] }, b1l[2] = { rvl[2], rvl[3] };
                hmma(o[2 * np], ph[kf], b0h);
                hmma(o[2 * np], pl[kf], b0h);
                hmma(o[2 * np], ph[kf], b0l);
                hmma(o[2 * np + 1], ph[kf], b1h);
                hmma(o[2 * np + 1], pl[kf], b1h);
                hmma(o[2 * np + 1], ph[kf], b1l);
            }
        }

        __syncthreads();
        issue(kt + 2);
    }

    // ---- epilogue: normalize + bf16 split to [M][D] ----
    const float inv_l = 1.f / l_l;
    const float inv_h = 1.f / l_h;
    const int grl = qt * 64 + w * 16 + rl;
    const int grh = grl + 8;
    const size_t basel = ((size_t)b * S_ + grl) * D_ + h * HD_;
    const size_t baseh = ((size_t)b * S_ + grh) * D_ + h * HD_;
#pragma unroll
    for (int nt = 0; nt < 16; nt++) {
        const int hd0 = nt * 8 + cq;
        uint32_t hp, lp;
        split2(o[nt][0] * inv_l, o[nt][1] * inv_l, hp, lp);
        *(uint32_t*)(ohi + basel + hd0) = hp;
        *(uint32_t*)(olo + basel + hd0) = lp;
        split2(o[nt][2] * inv_h, o[nt][3] * inv_h, hp, lp);
        *(uint32_t*)(ohi + baseh + hd0) = hp;
        *(uint32_t*)(olo + baseh + hd0) = lp;
    }
}

// ---------------- launcher ----------------
extern "C" void kernel_launch(void* const* d_in, const int* in_sizes, int n_in,
                              void* d_out, int out_size)
{
    (void)in_sizes; (void)n_in; (void)out_size;
    const float* x    = (const float*)d_in[0];
    const float* rsin = (const float*)d_in[2];
    const float* rcos = (const float*)d_in[3];
    const float* wqkv = (const float*)d_in[4];
    const float* wo   = (const float*)d_in[5];
    const float* n1   = (const float*)d_in[6];
    const float* n2   = (const float*)d_in[7];
    const float* wk   = (const float*)d_in[8];
    const float* wv   = (const float*)d_in[9];
    float* out = (float*)d_out;

    float *p_qkv, *p_x1;
    __nv_bfloat16 *p_qh, *p_ql, *p_kh, *p_kl, *p_vh, *p_vl;
    __nv_bfloat16 *p_xn_hi, *p_xn_lo, *p_at_hi, *p_at_lo, *p_h_hi, *p_h_lo;
    __nv_bfloat16 *p_wqkv_hi, *p_wqkv_lo, *p_wo_hi, *p_wo_lo, *p_wk_hi, *p_wk_lo, *p_wv_hi, *p_wv_lo;
    cudaGetSymbolAddress((void**)&p_qkv, g_qkv);
    cudaGetSymbolAddress((void**)&p_x1, g_x1);
    cudaGetSymbolAddress((void**)&p_qh, g_qh);
    cudaGetSymbolAddress((void**)&p_ql, g_ql);
    cudaGetSymbolAddress((void**)&p_kh, g_kh);
    cudaGetSymbolAddress((void**)&p_kl, g_kl);
    cudaGetSymbolAddress((void**)&p_vh, g_vh);
    cudaGetSymbolAddress((void**)&p_vl, g_vl);
    cudaGetSymbolAddress((void**)&p_xn_hi, g_xn_hi);
    cudaGetSymbolAddress((void**)&p_xn_lo, g_xn_lo);
    cudaGetSymbolAddress((void**)&p_at_hi, g_at_hi);
    cudaGetSymbolAddress((void**)&p_at_lo, g_at_lo);
    cudaGetSymbolAddress((void**)&p_h_hi, g_h_hi);
    cudaGetSymbolAddress((void**)&p_h_lo, g_h_lo);
    cudaGetSymbolAddress((void**)&p_wqkv_hi, g_wqkv_hi);
    cudaGetSymbolAddress((void**)&p_wqkv_lo, g_wqkv_lo);
    cudaGetSymbolAddress((void**)&p_wo_hi, g_wo_hi);
    cudaGetSymbolAddress((void**)&p_wo_lo, g_wo_lo);
    cudaGetSymbolAddress((void**)&p_wk_hi, g_wk_hi);
    cudaGetSymbolAddress((void**)&p_wk_lo, g_wk_lo);
    cudaGetSymbolAddress((void**)&p_wv_hi, g_wv_hi);
    cudaGetSymbolAddress((void**)&p_wv_lo, g_wv_lo);

    cudaFuncSetAttribute(flash_kernel, cudaFuncAttributeMaxDynamicSharedMemorySize, FLASH_SMEM);
    cudaFuncSetAttribute(mma_gemm<0>, cudaFuncAttributeMaxDynamicSharedMemorySize, GEMM_SMEM);
    cudaFuncSetAttribute(mma_gemm<1>, cudaFuncAttributeMaxDynamicSharedMemorySize, GEMM_SMEM);
    cudaFuncSetAttribute(mma_gemm<2>, cudaFuncAttributeMaxDynamicSharedMemorySize, GEMM_SMEM);

    const dim3 tb(32, 8);
    wsplit_kernel<<<dim3(QKVN / 32, D_ / 32), tb>>>(wqkv, p_wqkv_hi, p_wqkv_lo, D_, QKVN);
    wsplit_kernel<<<dim3(D_ / 32, D_ / 32), tb>>>(wo, p_wo_hi, p_wo_lo, D_, D_);
    wsplit_kernel<<<dim3(FF_ / 32, D_ / 32), tb>>>(wk, p_wk_hi, p_wk_lo, D_, FF_);
    wsplit_kernel<<<dim3(D_ / 32, FF_ / 32), tb>>>(wv, p_wv_hi, p_wv_lo, FF_, D_);

    // x1 = x + attn(rmsnorm(x))
    rmsnorm_bf_kernel<<<M_, 256>>>(x, n1, p_xn_hi, p_xn_lo);
    mma_gemm<0><<<dim3(QKVN / 256, M_ / 128), 256, GEMM_SMEM>>>(
        p_xn_hi, p_xn_lo, p_wqkv_hi, p_wqkv_lo, nullptr, p_qkv, nullptr, nullptr, QKVN, D_);
    rope_kernel<<<M_, 256>>>(p_qkv, rsin, rcos, p_qh, p_ql, p_kh, p_kl, p_vh, p_vl);
    flash_kernel<<<dim3(S_ / 64, QC_, B_), 128, FLASH_SMEM>>>(
        p_qh, p_ql, p_kh, p_kl, p_vh, p_vl, p_at_hi, p_at_lo);
    mma_gemm<1><<<dim3(D_ / 256, M_ / 128), 256, GEMM_SMEM>>>(
        p_at_hi, p_at_lo, p_wo_hi, p_wo_lo, x, p_x1, nullptr, nullptr, D_, D_);

    // out = x1 + ffn(rmsnorm(x1))
    rmsnorm_bf_kernel<<<M_, 256>>>(p_x1, n2, p_xn_hi, p_xn_lo);
    mma_gemm<2><<<dim3(FF_ / 256, M_ / 128), 256, GEMM_SMEM>>>(
        p_xn_hi, p_xn_lo, p_wk_hi, p_wk_lo, nullptr, nullptr, p_h_hi, p_h_lo, FF_, D_);
    mma_gemm<1><<<dim3(D_ / 256, M_ / 128), 256, GEMM_SMEM>>>(
        p_h_hi, p_h_lo, p_wv_hi, p_wv_lo, p_x1, out, nullptr, nullptr, D_, FF_);
}

// round 5
// speedup vs baseline: 3.6962x; 1.4281x over previous
#include <cuda_runtime.h>
#include <cuda_fp16.h>
#include <cstdint>
#include <cstddef>

#define B_   2
#define S_   2048
#define D_   2048
#define QC_  16
#define KVC_ 4
#define HD_  128
#define FF_  8192
#define M_   (B_ * S_)             // 4096
#define QKVN (D_ + 2 * KVC_ * HD_) // 3072

// ---------------- scratch ----------------
__device__ float g_qkv [(size_t)M_ * QKVN];
__device__ float g_x1  [(size_t)M_ * D_];
__device__ __half g_qh [(size_t)B_ * QC_  * S_ * HD_];
__device__ __half g_ql [(size_t)B_ * QC_  * S_ * HD_];
__device__ __half g_k  [(size_t)B_ * KVC_ * S_ * HD_];
__device__ __half g_v  [(size_t)B_ * KVC_ * S_ * HD_];
__device__ __half g_xn_hi [(size_t)M_ * D_];
__device__ __half g_xn_lo [(size_t)M_ * D_];
__device__ __half g_at_hi [(size_t)M_ * D_];
__device__ __half g_at_lo [(size_t)M_ * D_];
__device__ __half g_h_hi  [(size_t)M_ * FF_];
__device__ __half g_h_lo  [(size_t)M_ * FF_];
__device__ __half g_wqkv [(size_t)QKVN * D_];
__device__ __half g_wo   [(size_t)D_ * D_];
__device__ __half g_wk   [(size_t)FF_ * D_];
__device__ __half g_wv   [(size_t)D_ * FF_];

// ---------------- helpers ----------------
__device__ __forceinline__ uint32_t smem_u32(const void* p) {
    uint32_t a;
    asm("{ .reg .u64 t; cvta.to.shared.u64 t, %1; cvt.u32.u64 %0, t; }" : "=r"(a) : "l"(p));
    return a;
}
// split two floats -> (hi f16x2, lo f16x2)
__device__ __forceinline__ void split2h(float x, float y, uint32_t& hi, uint32_t& lo) {
    __half2 h = __floats2half2_rn(x, y);
    const float hx = __half2float(__low2half(h));
    const float hy = __half2float(__high2half(h));
    __half2 l = __floats2half2_rn(x - hx, y - hy);
    hi = *(uint32_t*)&h;
    lo = *(uint32_t*)&l;
}
__device__ __forceinline__ uint32_t packh(float x, float y) {
    __half2 h = __floats2half2_rn(x, y);
    return *(uint32_t*)&h;
}
__device__ __forceinline__ float ex2(float x) {
    float y;
    asm("ex2.approx.f32 %0, %1;" : "=f"(y) : "f"(x));
    return y;
}

#define SW(o) (((uint32_t)(o)) ^ ((((uint32_t)(o)) >> 3) & 0x70u))

__device__ __forceinline__ void ldsm4(uint32_t* r, uint32_t addr) {
    asm volatile("ldmatrix.sync.aligned.m8n8.x4.shared.b16 {%0,%1,%2,%3},[%4];"
                 : "=r"(r[0]), "=r"(r[1]), "=r"(r[2]), "=r"(r[3]) : "r"(addr));
}
__device__ __forceinline__ void ldsm4t(uint32_t* r, uint32_t addr) {
    asm volatile("ldmatrix.sync.aligned.m8n8.x4.trans.shared.b16 {%0,%1,%2,%3},[%4];"
                 : "=r"(r[0]), "=r"(r[1]), "=r"(r[2]), "=r"(r[3]) : "r"(addr));
}
__device__ __forceinline__ void hmma(float* c, const uint32_t* a, const uint32_t* b) {
    asm volatile("mma.sync.aligned.m16n8k16.row.col.f32.f16.f16.f32 "
                 "{%0,%1,%2,%3},{%4,%5,%6,%7},{%8,%9},{%0,%1,%2,%3};"
                 : "+f"(c[0]), "+f"(c[1]), "+f"(c[2]), "+f"(c[3])
                 : "r"(a[0]), "r"(a[1]), "r"(a[2]), "r"(a[3]), "r"(b[0]), "r"(b[1]));
}
__device__ __forceinline__ void cpa(uint32_t dst, const void* src) {
    asm volatile("cp.async.cg.shared.global [%0],[%1],16;" :: "r"(dst), "l"(src));
}

// ---------------- RMSNorm -> fp16 hi/lo ----------------
__global__ __launch_bounds__(256) void rmsnorm_h_kernel(
    const float* __restrict__ x, const float* __restrict__ w,
    __half* __restrict__ ohi, __half* __restrict__ olo)
{
    const int row = blockIdx.x;
    const int tid = threadIdx.x;
    const float4* xr = (const float4*)(x + (size_t)row * D_);
    float4 vals[2];
    float ss = 0.f;
#pragma unroll
    for (int i = 0; i < 2; i++) {
        float4 v = xr[tid + 256 * i];
        vals[i] = v;
        ss += v.x * v.x + v.y * v.y + v.z * v.z + v.w * v.w;
    }
#pragma unroll
    for (int sh = 16; sh > 0; sh >>= 1) ss += __shfl_xor_sync(0xffffffffu, ss, sh);
    __shared__ float red[8];
    if ((tid & 31) == 0) red[tid >> 5] = ss;
    __syncthreads();
    float tot = 0.f;
#pragma unroll
    for (int i = 0; i < 8; i++) tot += red[i];
    const float rs = rsqrtf(tot * (1.f / (float)D_) + 1e-5f);
    const float4* w4 = (const float4*)w;
#pragma unroll
    for (int i = 0; i < 2; i++) {
        float4 v = vals[i], ww = w4[tid + 256 * i];
        const size_t base = (size_t)row * D_ + (tid + 256 * i) * 4;
        uint32_t h0, l0, h1, l1;
        split2h(v.x * rs * ww.x, v.y * rs * ww.y, h0, l0);
        split2h(v.z * rs * ww.z, v.w * rs * ww.w, h1, l1);
        *(uint32_t*)(ohi + base) = h0;
        *(uint32_t*)(ohi + base + 2) = h1;
        *(uint32_t*)(olo + base) = l0;
        *(uint32_t*)(olo + base + 2) = l1;
    }
}

// ---------------- weight transpose + fp16 convert: W[K,N] -> Wt[N,K] ----------
__global__ __launch_bounds__(256) void wcvt_kernel(
    const float* __restrict__ W, __half* __restrict__ out, int K, int N)
{
    __shared__ float t[32][33];
    const int tx = threadIdx.x, ty = threadIdx.y;
    const int n0 = blockIdx.x * 32, k0 = blockIdx.y * 32;
#pragma unroll
    for (int j = 0; j < 4; j++)
        t[ty + 8 * j][tx] = W[(size_t)(k0 + ty + 8 * j) * N + n0 + tx];
    __syncthreads();
#pragma unroll
    for (int j = 0; j < 4; j++)
        out[(size_t)(n0 + ty + 8 * j) * K + k0 + tx] = __float2half(t[tx][ty + 8 * j]);
}

// ---------------- RoPE -> fp16 q(hi/lo), k, v ----------------
__global__ __launch_bounds__(256) void rope_kernel(
    const float* __restrict__ qkv, const float* __restrict__ rsin,
    const float* __restrict__ rcos,
    __half* __restrict__ qh, __half* __restrict__ ql,
    __half* __restrict__ k, __half* __restrict__ v)
{
    const int t = blockIdx.x;
    const int b = t / S_;
    const int s = t % S_;
    const int tid = threadIdx.x;
    const float* row = qkv + (size_t)t * QKVN;
    const float* sinr = rsin + (size_t)s * HD_;
    const float* cosr = rcos + (size_t)s * HD_;
    // q: split fp16
    for (int p = tid; p < 1024; p += 256) {
        const int h = p >> 6, pp = p & 63;
        const float x0 = row[2 * p], x1 = row[2 * p + 1];
        const float sn = sinr[2 * pp], cs = cosr[2 * pp];
        const size_t o = (((size_t)(b * QC_ + h)) * S_ + s) * HD_ + 2 * pp;
        uint32_t hp, lp;
        split2h(x0 * cs - x1 * sn, x1 * cs + x0 * sn, hp, lp);
        *(uint32_t*)(qh + o) = hp;
        *(uint32_t*)(ql + o) = lp;
    }
    // k: plain fp16, pre-scaled by HD^-0.5 * log2(e)
    const float ks = 0.08838834764831845f * 1.4426950408889634f;
    for (int p = tid; p < 256; p += 256) {
        const int h = p >> 6, pp = p & 63;
        const float x0 = row[D_ + 2 * p], x1 = row[D_ + 2 * p + 1];
        const float sn = sinr[2 * pp], cs = cosr[2 * pp];
        const size_t o = (((size_t)(b * KVC_ + h)) * S_ + s) * HD_ + 2 * pp;
        *(uint32_t*)(k + o) = packh((x0 * cs - x1 * sn) * ks, (x1 * cs + x0 * sn) * ks);
    }
    // v: plain fp16
    for (int e = tid; e < 256; e += 256) {
        const int h = e >> 6, d = (e & 63) * 2;
        const size_t o = (((size_t)(b * KVC_ + h)) * S_ + s) * HD_ + d;
        *(uint32_t*)(v + o) = packh(row[D_ + 512 + e * 2], row[D_ + 512 + e * 2 + 1]);
    }
}

// ---------------- HMMA GEMM: CTA 128x256, warp 64x64, fp16 2-pass ----------------
#define PIPE 3
#define STG  65536
#define OF_AH 0
#define OF_AL 16384
#define OF_B  32768
#define GEMM_SMEM (PIPE * STG)

template <int EPI>
__global__ __launch_bounds__(256) void mma_gemm(
    const __half* __restrict__ Ahi, const __half* __restrict__ Alo,
    const __half* __restrict__ Bw,
    const float* __restrict__ R, float* __restrict__ Cf,
    __half* __restrict__ Chi, __half* __restrict__ Clo,
    int N, int K)
{
    extern __shared__ char smem[];
    const uint32_t sb = smem_u32(smem);
    const int tid = threadIdx.x;
    const int wid = tid >> 5, lane = tid & 31;
    const int wm = wid & 1, wn = wid >> 1;
    const int bm = blockIdx.y * 128, bn = blockIdx.x * 256;
    const int NC = K >> 6;

    float acc[4][8][4];
#pragma unroll
    for (int i = 0; i < 4; i++)
#pragma unroll
        for (int j = 0; j < 8; j++)
#pragma unroll
            for (int q = 0; q < 4; q++) acc[i][j][q] = 0.f;

    auto issue = [&](int c) {
        if (c < NC) {
            const int kc = c << 6;
            const uint32_t st = sb + (uint32_t)(c % PIPE) * STG;
            const char* pa_hi = (const char*)(Ahi + (size_t)bm * K + kc);
            const char* pa_lo = (const char*)(Alo + (size_t)bm * K + kc);
            const char* pb    = (const char*)(Bw  + (size_t)bn * K + kc);
#pragma unroll
            for (int i = 0; i < 4; i++) {
                const int idx = tid + 256 * i;
                const int r = idx >> 3;
                const uint32_t ch = (idx & 7) << 4;
                const uint32_t so = SW(r * 128 + ch);
                const size_t go = (size_t)r * (K * 2) + ch;
                cpa(st + OF_AH + so, pa_hi + go);
                cpa(st + OF_AL + so, pa_lo + go);
            }
#pragma unroll
            for (int i = 0; i < 8; i++) {
                const int idx = tid + 256 * i;
                const int r = idx >> 3;
                const uint32_t ch = (idx & 7) << 4;
                cpa(st + OF_B + SW(r * 128 + ch), pb + (size_t)r * (K * 2) + ch);
            }
        }
        asm volatile("cp.async.commit_group;");
    };

    issue(0);
    issue(1);
    issue(2);

    const uint32_t arow = (uint32_t)(wm * 64 + (lane & 15));
    const uint32_t brow = (uint32_t)(wn * 64 + (lane & 15));
    const uint32_t khalf = ((uint32_t)lane >> 4) << 4;

    for (int c = 0; c < NC; c++) {
        asm volatile("cp.async.wait_group 2;" ::: "memory");
        __syncthreads();
        const uint32_t st = sb + (uint32_t)(c % PIPE) * STG;
#pragma unroll
        for (int ks = 0; ks < 4; ks++) {
            const uint32_t col = (uint32_t)ks * 32 + khalf;
            uint32_t ah[4][4], al[4][4];
#pragma unroll
            for (int mt = 0; mt < 4; mt++) {
                const uint32_t off = SW((arow + mt * 16) * 128 + col);
                ldsm4(ah[mt], st + OF_AH + off);
                ldsm4(al[mt], st + OF_AL + off);
            }
#pragma unroll
            for (int ntp = 0; ntp < 4; ntp++) {
                uint32_t rh[4];
                ldsm4(rh, st + OF_B + SW((brow + ntp * 16) * 128 + col));
                uint32_t b0[2] = { rh[0], rh[2] }, b1[2] = { rh[1], rh[3] };
#pragma unroll
                for (int mt = 0; mt < 4; mt++) {
                    hmma(acc[mt][2 * ntp],     ah[mt], b0);
                    hmma(acc[mt][2 * ntp],     al[mt], b0);
                    hmma(acc[mt][2 * ntp + 1], ah[mt], b1);
                    hmma(acc[mt][2 * ntp + 1], al[mt], b1);
                }
            }
        }
        __syncthreads();
        issue(c + 3);
    }

    // epilogue
    const int row0 = bm + wm * 64 + (lane >> 2);
    const int col0 = bn + wn * 64 + ((lane & 3) << 1);
#pragma unroll
    for (int mt = 0; mt < 4; mt++) {
#pragma unroll
        for (int nt = 0; nt < 8; nt++) {
            const int r0 = row0 + mt * 16;
            const int cc = col0 + nt * 8;
            if (EPI <= 1) {
                float2 v0 = make_float2(acc[mt][nt][0], acc[mt][nt][1]);
                float2 v1 = make_float2(acc[mt][nt][2], acc[mt][nt][3]);
                if (EPI == 1) {
                    const float2 ra = *(const float2*)(R + (size_t)r0 * N + cc);
                    const float2 rb = *(const float2*)(R + (size_t)(r0 + 8) * N + cc);
                    v0.x += ra.x; v0.y += ra.y;
                    v1.x += rb.x; v1.y += rb.y;
                }
                *(float2*)(Cf + (size_t)r0 * N + cc) = v0;
                *(float2*)(Cf + (size_t)(r0 + 8) * N + cc) = v1;
            } else {
#pragma unroll
                for (int half = 0; half < 2; half++) {
                    float v0 = acc[mt][nt][2 * half + 0];
                    float v1 = acc[mt][nt][2 * half + 1];
                    v0 = fmaxf(v0, 0.f); v0 *= v0;
                    v1 = fmaxf(v1, 0.f); v1 *= v1;
                    uint32_t hp, lp;
                    split2h(v0, v1, hp, lp);
                    const size_t o = (size_t)(r0 + 8 * half) * N + cc;
                    *(uint32_t*)(Chi + o) = hp;
                    *(uint32_t*)(Clo + o) = lp;
                }
            }
        }
    }
}

// ---------------- HMMA flash attention (fp16, Q/P split 2-pass) ----------
#define FL_QH 0
#define FL_QL 16384
#define FL_ST(s) (32768 + (s) * 32768)
#define FL_K 0
#define FL_V 16384
#define FLASH_SMEM (32768 + 2 * 32768)

// smem tile offset: [2 hd-halves][64 rows][128B], swizzled
__device__ __forceinline__ uint32_t floff(uint32_t r, uint32_t hb) {
    return (hb >> 7) * 8192 + r * 128 + ((hb & 127) ^ ((r & 7) << 4));
}

__global__ __launch_bounds__(128) void flash_kernel(
    const __half* __restrict__ qh, const __half* __restrict__ ql,
    const __half* __restrict__ kk, const __half* __restrict__ vv,
    __half* __restrict__ ohi, __half* __restrict__ olo)
{
    extern __shared__ char smem[];
    const uint32_t sb = smem_u32(smem);
    const int tid = threadIdx.x;
    const int w = tid >> 5, lane = tid & 31;
    const int qt = (int)(gridDim.x - 1 - blockIdx.x);
    const int h = blockIdx.y;
    const int b = blockIdx.z;
    const int kvh = h & 3;

    const __half* qbh = qh + (((size_t)(b * QC_ + h)) * S_ + qt * 64) * HD_;
    const __half* qbl = ql + (((size_t)(b * QC_ + h)) * S_ + qt * 64) * HD_;
    const size_t kvbase = ((size_t)(b * KVC_ + kvh)) * S_ * HD_;

    auto ldtile = [&](uint32_t dst, const __half* src) {
#pragma unroll
        for (int i = 0; i < 8; i++) {
            const int idx = tid + 128 * i;
            const uint32_t r = (uint32_t)idx >> 4;
            const uint32_t hb = ((uint32_t)idx & 15) << 4;
            cpa(dst + floff(r, hb), (const char*)src + (size_t)r * 256 + hb);
        }
    };
    auto issue = [&](int kt) {
        if (kt <= qt) {
            const uint32_t st = sb + FL_ST(kt & 1);
            ldtile(st + FL_K, kk + kvbase + (size_t)kt * 64 * HD_);
            ldtile(st + FL_V, vv + kvbase + (size_t)kt * 64 * HD_);
        }
        asm volatile("cp.async.commit_group;");
    };

    ldtile(sb + FL_QH, qbh);
    ldtile(sb + FL_QL, qbl);
    issue(0);
    issue(1);

    float o[16][4];
#pragma unroll
    for (int i = 0; i < 16; i++)
#pragma unroll
        for (int j = 0; j < 4; j++) o[i][j] = 0.f;
    float m_l = -1e30f, m_h = -1e30f, l_l = 0.f, l_h = 0.f;

    const uint32_t arow = (uint32_t)(w * 16 + (lane & 15));
    const uint32_t khalf = ((uint32_t)lane >> 4) << 4;
    const int rl = lane >> 2;
    const int cq = (lane & 3) << 1;

    for (int kt = 0; kt <= qt; kt++) {
        asm volatile("cp.async.wait_group 1;" ::: "memory");
        __syncthreads();
        const uint32_t st = sb + FL_ST(kt & 1);

        // ---- S = Q K^T (2-pass), log2-domain logits ----
        float sacc[8][4];
#pragma unroll
        for (int i = 0; i < 8; i++)
#pragma unroll
            for (int j = 0; j < 4; j++) sacc[i][j] = 0.f;

#pragma unroll
        for (int ks = 0; ks < 8; ks++) {
            const uint32_t hb = (uint32_t)ks * 32 + khalf;
            uint32_t aqh[4], aql[4];
            ldsm4(aqh, sb + FL_QH + floff(arow, hb));
            ldsm4(aql, sb + FL_QL + floff(arow, hb));
#pragma unroll
            for (int ntp = 0; ntp < 4; ntp++) {
                const uint32_t krow = (uint32_t)(ntp * 16) + (lane & 15);
                uint32_t rh[4];
                ldsm4(rh, st + FL_K + floff(krow, hb));
                uint32_t b0[2] = { rh[0], rh[2] }, b1[2] = { rh[1], rh[3] };
                hmma(sacc[2 * ntp],     aqh, b0);
                hmma(sacc[2 * ntp],     aql, b0);
                hmma(sacc[2 * ntp + 1], aqh, b1);
                hmma(sacc[2 * ntp + 1], aql, b1);
            }
        }

        // ---- causal mask ----
        if (kt == qt) {
            const int rowl = w * 16 + rl;
            const int rowh = rowl + 8;
#pragma unroll
            for (int nt = 0; nt < 8; nt++) {
                const int c0 = nt * 8 + cq, c1 = c0 + 1;
                if (c0 > rowl) sacc[nt][0] = -1e30f;
                if (c1 > rowl) sacc[nt][1] = -1e30f;
                if (c0 > rowh) sacc[nt][2] = -1e30f;
                if (c1 > rowh) sacc[nt][3] = -1e30f;
            }
        }

        // ---- online softmax (base-2) ----
        float mx_l = -1e30f, mx_h = -1e30f;
#pragma unroll
        for (int nt = 0; nt < 8; nt++) {
            mx_l = fmaxf(mx_l, fmaxf(sacc[nt][0], sacc[nt][1]));
            mx_h = fmaxf(mx_h, fmaxf(sacc[nt][2], sacc[nt][3]));
        }
#pragma unroll
        for (int sh = 1; sh < 4; sh <<= 1) {
            mx_l = fmaxf(mx_l, __shfl_xor_sync(0xffffffffu, mx_l, sh));
            mx_h = fmaxf(mx_h, __shfl_xor_sync(0xffffffffu, mx_h, sh));
        }
        const float mn_l = fmaxf(m_l, mx_l);
        const float mn_h = fmaxf(m_h, mx_h);
        const float sc_l = ex2(m_l - mn_l);
        const float sc_h = ex2(m_h - mn_h);
        m_l = mn_l;
        m_h = mn_h;

        float sum_l = 0.f, sum_h = 0.f;
#pragma unroll
        for (int nt = 0; nt < 8; nt++) {
            sacc[nt][0] = ex2(sacc[nt][0] - mn_l);
            sacc[nt][1] = ex2(sacc[nt][1] - mn_l);
            sacc[nt][2] = ex2(sacc[nt][2] - mn_h);
            sacc[nt][3] = ex2(sacc[nt][3] - mn_h);
            sum_l += sacc[nt][0] + sacc[nt][1];
            sum_h += sacc[nt][2] + sacc[nt][3];
        }
#pragma unroll
        for (int sh = 1; sh < 4; sh <<= 1) {
            sum_l += __shfl_xor_sync(0xffffffffu, sum_l, sh);
            sum_h += __shfl_xor_sync(0xffffffffu, sum_h, sh);
        }
        l_l = l_l * sc_l + sum_l;
        l_h = l_h * sc_h + sum_h;
#pragma unroll
        for (int i = 0; i < 16; i++) {
            o[i][0] *= sc_l; o[i][1] *= sc_l;
            o[i][2] *= sc_h; o[i][3] *= sc_h;
        }

        // ---- P frags (split fp16) ----
        uint32_t ph[4][4], pl[4][4];
#pragma unroll
        for (int kf = 0; kf < 4; kf++) {
            split2h(sacc[2 * kf][0], sacc[2 * kf][1], ph[kf][0], pl[kf][0]);
            split2h(sacc[2 * kf][2], sacc[2 * kf][3], ph[kf][1], pl[kf][1]);
            split2h(sacc[2 * kf + 1][0], sacc[2 * kf + 1][1], ph[kf][2], pl[kf][2]);
            split2h(sacc[2 * kf + 1][2], sacc[2 * kf + 1][3], ph[kf][3], pl[kf][3]);
        }

        // ---- O += P V (2-pass) ----
#pragma unroll
        for (int kf = 0; kf < 4; kf++) {
            const uint32_t vrow = (uint32_t)(kf * 16) + (lane & 7) + (((uint32_t)lane >> 3) & 1) * 8;
#pragma unroll
            for (int np = 0; np < 8; np++) {
                const uint32_t hb = (uint32_t)np * 32 + khalf;
                uint32_t rv[4];
                ldsm4t(rv, st + FL_V + floff(vrow, hb));
                uint32_t b0[2] = { rv[0], rv[1] }, b1[2] = { rv[2], rv[3] };
                hmma(o[2 * np],     ph[kf], b0);
                hmma(o[2 * np],     pl[kf], b0);
                hmma(o[2 * np + 1], ph[kf], b1);
                hmma(o[2 * np + 1], pl[kf], b1);
            }
        }

        __syncthreads();
        issue(kt + 2);
    }

    // ---- epilogue ----
    const float inv_l = 1.f / l_l;
    const float inv_h = 1.f / l_h;
    const int grl = qt * 64 + w * 16 + rl;
    const int grh = grl + 8;
    const size_t basel = ((size_t)b * S_ + grl) * D_ + h * HD_;
    const size_t baseh = ((size_t)b * S_ + grh) * D_ + h * HD_;
#pragma unroll
    for (int nt = 0; nt < 16; nt++) {
        const int hd0 = nt * 8 + cq;
        uint32_t hp, lp;
        split2h(o[nt][0] * inv_l, o[nt][1] * inv_l, hp, lp);
        *(uint32_t*)(ohi + basel + hd0) = hp;
        *(uint32_t*)(olo + basel + hd0) = lp;
        split2h(o[nt][2] * inv_h, o[nt][3] * inv_h, hp, lp);
        *(uint32_t*)(ohi + baseh + hd0) = hp;
        *(uint32_t*)(olo + baseh + hd0) = lp;
    }
}

// ---------------- launcher ----------------
extern "C" void kernel_launch(void* const* d_in, const int* in_sizes, int n_in,
                              void* d_out, int out_size)
{
    (void)in_sizes; (void)n_in; (void)out_size;
    const float* x    = (const float*)d_in[0];
    const float* rsin = (const float*)d_in[2];
    const float* rcos = (const float*)d_in[3];
    const float* wqkv = (const float*)d_in[4];
    const float* wo   = (const float*)d_in[5];
    const float* n1   = (const float*)d_in[6];
    const float* n2   = (const float*)d_in[7];
    const float* wk   = (const float*)d_in[8];
    const float* wv   = (const float*)d_in[9];
    float* out = (float*)d_out;

    float *p_qkv, *p_x1;
    __half *p_qh, *p_ql, *p_k, *p_v;
    __half *p_xn_hi, *p_xn_lo, *p_at_hi, *p_at_lo, *p_h_hi, *p_h_lo;
    __half *p_wqkv, *p_wo, *p_wk, *p_wv;
    cudaGetSymbolAddress((void**)&p_qkv, g_qkv);
    cudaGetSymbolAddress((void**)&p_x1, g_x1);
    cudaGetSymbolAddress((void**)&p_qh, g_qh);
    cudaGetSymbolAddress((void**)&p_ql, g_ql);
    cudaGetSymbolAddress((void**)&p_k, g_k);
    cudaGetSymbolAddress((void**)&p_v, g_v);
    cudaGetSymbolAddress((void**)&p_xn_hi, g_xn_hi);
    cudaGetSymbolAddress((void**)&p_xn_lo, g_xn_lo);
    cudaGetSymbolAddress((void**)&p_at_hi, g_at_hi);
    cudaGetSymbolAddress((void**)&p_at_lo, g_at_lo);
    cudaGetSymbolAddress((void**)&p_h_hi, g_h_hi);
    cudaGetSymbolAddress((void**)&p_h_lo, g_h_lo);
    cudaGetSymbolAddress((void**)&p_wqkv, g_wqkv);
    cudaGetSymbolAddress((void**)&p_wo, g_wo);
    cudaGetSymbolAddress((void**)&p_wk, g_wk);
    cudaGetSymbolAddress((void**)&p_wv, g_wv);

    cudaFuncSetAttribute(flash_kernel, cudaFuncAttributeMaxDynamicSharedMemorySize, FLASH_SMEM);
    cudaFuncSetAttribute(mma_gemm<0>, cudaFuncAttributeMaxDynamicSharedMemorySize, GEMM_SMEM);
    cudaFuncSetAttribute(mma_gemm<1>, cudaFuncAttributeMaxDynamicSharedMemorySize, GEMM_SMEM);
    cudaFuncSetAttribute(mma_gemm<2>, cudaFuncAttributeMaxDynamicSharedMemorySize, GEMM_SMEM);

    const dim3 tb(32, 8);
    wcvt_kernel<<<dim3(QKVN / 32, D_ / 32), tb>>>(wqkv, p_wqkv, D_, QKVN);
    wcvt_kernel<<<dim3(D_ / 32, D_ / 32), tb>>>(wo, p_wo, D_, D_);
    wcvt_kernel<<<dim3(FF_ / 32, D_ / 32), tb>>>(wk, p_wk, D_, FF_);
    wcvt_kernel<<<dim3(D_ / 32, FF_ / 32), tb>>>(wv, p_wv, FF_, D_);

    // x1 = x + attn(rmsnorm(x))
    rmsnorm_h_kernel<<<M_, 256>>>(x, n1, p_xn_hi, p_xn_lo);
    mma_gemm<0><<<dim3(QKVN / 256, M_ / 128), 256, GEMM_SMEM>>>(
        p_xn_hi, p_xn_lo, p_wqkv, nullptr, p_qkv, nullptr, nullptr, QKVN, D_);
    rope_kernel<<<M_, 256>>>(p_qkv, rsin, rcos, p_qh, p_ql, p_k, p_v);
    flash_kernel<<<dim3(S_ / 64, QC_, B_), 128, FLASH_SMEM>>>(
        p_qh, p_ql, p_k, p_v, p_at_hi, p_at_lo);
    mma_gemm<1><<<dim3(D_ / 256, M_ / 128), 256, GEMM_SMEM>>>(
        p_at_hi, p_at_lo, p_wo, x, p_x1, nullptr, nullptr, D_, D_);

    // out = x1 + ffn(rmsnorm(x1))
    rmsnorm_h_kernel<<<M_, 256>>>(p_x1, n2, p_xn_hi, p_xn_lo);
    mma_gemm<2><<<dim3(FF_ / 256, M_ / 128), 256, GEMM_SMEM>>>(
        p_xn_hi, p_xn_lo, p_wk, nullptr, nullptr, p_h_hi, p_h_lo, FF_, D_);
    mma_gemm<1><<<dim3(D_ / 256, M_ / 128), 256, GEMM_SMEM>>>(
        p_h_hi, p_h_lo, p_wv, p_x1, out, nullptr, nullptr, D_, FF_);
}

// round 6
// speedup vs baseline: 6.4649x; 1.7491x over previous
#include <cuda_runtime.h>
#include <cuda_fp16.h>
#include <cstdint>
#include <cstddef>

#define B_   2
#define S_   2048
#define D_   2048
#define QC_  16
#define KVC_ 4
#define HD_  128
#define FF_  8192
#define M_   (B_ * S_)             // 4096
#define QKVN (D_ + 2 * KVC_ * HD_) // 3072

// ---------------- scratch ----------------
__device__ float g_x1  [(size_t)M_ * D_];
__device__ __half g_qh [(size_t)B_ * QC_  * S_ * HD_];
__device__ __half g_ql [(size_t)B_ * QC_  * S_ * HD_];
__device__ __half g_k  [(size_t)B_ * KVC_ * S_ * HD_];
__device__ __half g_v  [(size_t)B_ * KVC_ * S_ * HD_];
__device__ __half g_xn [(size_t)M_ * D_];
__device__ __half g_at [(size_t)M_ * D_];
__device__ __half g_h  [(size_t)M_ * FF_];
__device__ __half g_wqkv [(size_t)QKVN * D_];
__device__ __half g_wo   [(size_t)D_ * D_];
__device__ __half g_wk   [(size_t)FF_ * D_];
__device__ __half g_wv   [(size_t)D_ * FF_];

// ---------------- helpers ----------------
__device__ __forceinline__ uint32_t smem_u32(const void* p) {
    uint32_t a;
    asm("{ .reg .u64 t; cvta.to.shared.u64 t, %1; cvt.u32.u64 %0, t; }" : "=r"(a) : "l"(p));
    return a;
}
__device__ __forceinline__ void split2h(float x, float y, uint32_t& hi, uint32_t& lo) {
    __half2 h = __floats2half2_rn(x, y);
    const float hx = __half2float(__low2half(h));
    const float hy = __half2float(__high2half(h));
    __half2 l = __floats2half2_rn(x - hx, y - hy);
    hi = *(uint32_t*)&h;
    lo = *(uint32_t*)&l;
}
__device__ __forceinline__ uint32_t packh(float x, float y) {
    __half2 h = __floats2half2_rn(x, y);
    return *(uint32_t*)&h;
}
__device__ __forceinline__ float ex2(float x) {
    float y;
    asm("ex2.approx.f32 %0, %1;" : "=f"(y) : "f"(x));
    return y;
}

#define SW(o) (((uint32_t)(o)) ^ ((((uint32_t)(o)) >> 3) & 0x70u))

__device__ __forceinline__ void ldsm4(uint32_t* r, uint32_t addr) {
    asm volatile("ldmatrix.sync.aligned.m8n8.x4.shared.b16 {%0,%1,%2,%3},[%4];"
                 : "=r"(r[0]), "=r"(r[1]), "=r"(r[2]), "=r"(r[3]) : "r"(addr));
}
__device__ __forceinline__ void ldsm4t(uint32_t* r, uint32_t addr) {
    asm volatile("ldmatrix.sync.aligned.m8n8.x4.trans.shared.b16 {%0,%1,%2,%3},[%4];"
                 : "=r"(r[0]), "=r"(r[1]), "=r"(r[2]), "=r"(r[3]) : "r"(addr));
}
__device__ __forceinline__ void hmma(float* c, const uint32_t* a, const uint32_t* b) {
    asm volatile("mma.sync.aligned.m16n8k16.row.col.f32.f16.f16.f32 "
                 "{%0,%1,%2,%3},{%4,%5,%6,%7},{%8,%9},{%0,%1,%2,%3};"
                 : "+f"(c[0]), "+f"(c[1]), "+f"(c[2]), "+f"(c[3])
                 : "r"(a[0]), "r"(a[1]), "r"(a[2]), "r"(a[3]), "r"(b[0]), "r"(b[1]));
}
__device__ __forceinline__ void cpa(uint32_t dst, const void* src) {
    asm volatile("cp.async.cg.shared.global [%0],[%1],16;" :: "r"(dst), "l"(src));
}

// ---------------- RMSNorm -> fp16 ----------------
__global__ __launch_bounds__(256) void rmsnorm_h_kernel(
    const float* __restrict__ x, const float* __restrict__ w,
    __half* __restrict__ o)
{
    const int row = blockIdx.x;
    const int tid = threadIdx.x;
    const float4* xr = (const float4*)(x + (size_t)row * D_);
    float4 vals[2];
    float ss = 0.f;
#pragma unroll
    for (int i = 0; i < 2; i++) {
        float4 v = xr[tid + 256 * i];
        vals[i] = v;
        ss += v.x * v.x + v.y * v.y + v.z * v.z + v.w * v.w;
    }
#pragma unroll
    for (int sh = 16; sh > 0; sh >>= 1) ss += __shfl_xor_sync(0xffffffffu, ss, sh);
    __shared__ float red[8];
    if ((tid & 31) == 0) red[tid >> 5] = ss;
    __syncthreads();
    float tot = 0.f;
#pragma unroll
    for (int i = 0; i < 8; i++) tot += red[i];
    const float rs = rsqrtf(tot * (1.f / (float)D_) + 1e-5f);
    const float4* w4 = (const float4*)w;
#pragma unroll
    for (int i = 0; i < 2; i++) {
        float4 v = vals[i], ww = w4[tid + 256 * i];
        const size_t base = (size_t)row * D_ + (tid + 256 * i) * 4;
        *(uint32_t*)(o + base)     = packh(v.x * rs * ww.x, v.y * rs * ww.y);
        *(uint32_t*)(o + base + 2) = packh(v.z * rs * ww.z, v.w * rs * ww.w);
    }
}

// ---------------- weight transpose + fp16 convert: W[K,N] -> Wt[N,K] ----------
__global__ __launch_bounds__(256) void wcvt_kernel(
    const float* __restrict__ W, __half* __restrict__ out, int K, int N)
{
    __shared__ float t[32][33];
    const int tx = threadIdx.x, ty = threadIdx.y;
    const int n0 = blockIdx.x * 32, k0 = blockIdx.y * 32;
#pragma unroll
    for (int j = 0; j < 4; j++)
        t[ty + 8 * j][tx] = W[(size_t)(k0 + ty + 8 * j) * N + n0 + tx];
    __syncthreads();
#pragma unroll
    for (int j = 0; j < 4; j++)
        out[(size_t)(n0 + ty + 8 * j) * K + k0 + tx] = __float2half(t[tx][ty + 8 * j]);
}

// ---------------- HMMA GEMM: CTA 128x256, warp 64x64, fp16 single-pass ----------
// EPI 1: Cf = acc + R ; EPI 2: Ch = half(relu(acc)^2) ;
// EPI 3: fused RoPE scatter to q(hi/lo)/k/v
#define PIPE 4
#define STG  49152
#define OF_A 0
#define OF_B 16384
#define GEMM_SMEM (PIPE * STG)

template <int EPI>
__global__ __launch_bounds__(256) void mma_gemm(
    const __half* __restrict__ A, const __half* __restrict__ Bw,
    const float* __restrict__ R, float* __restrict__ Cf,
    __half* __restrict__ Ch,
    const float* __restrict__ rsin, const float* __restrict__ rcos,
    __half* __restrict__ oqh, __half* __restrict__ oql,
    __half* __restrict__ okk, __half* __restrict__ ovv,
    int N, int K)
{
    extern __shared__ char smem[];
    const uint32_t sb = smem_u32(smem);
    const int tid = threadIdx.x;
    const int wid = tid >> 5, lane = tid & 31;
    const int wm = wid & 1, wn = wid >> 1;
    const int bm = blockIdx.y * 128, bn = blockIdx.x * 256;
    const int NC = K >> 6;

    float acc[4][8][4];
#pragma unroll
    for (int i = 0; i < 4; i++)
#pragma unroll
        for (int j = 0; j < 8; j++)
#pragma unroll
            for (int q = 0; q < 4; q++) acc[i][j][q] = 0.f;

    auto issue = [&](int c) {
        if (c < NC) {
            const int kc = c << 6;
            const uint32_t st = sb + (uint32_t)(c % PIPE) * STG;
            const char* pa = (const char*)(A  + (size_t)bm * K + kc);
            const char* pb = (const char*)(Bw + (size_t)bn * K + kc);
#pragma unroll
            for (int i = 0; i < 4; i++) {
                const int idx = tid + 256 * i;
                const int r = idx >> 3;
                const uint32_t ch = (idx & 7) << 4;
                cpa(st + OF_A + SW(r * 128 + ch), pa + (size_t)r * (K * 2) + ch);
            }
#pragma unroll
            for (int i = 0; i < 8; i++) {
                const int idx = tid + 256 * i;
                const int r = idx >> 3;
                const uint32_t ch = (idx & 7) << 4;
                cpa(st + OF_B + SW(r * 128 + ch), pb + (size_t)r * (K * 2) + ch);
            }
        }
        asm volatile("cp.async.commit_group;");
    };

    issue(0); issue(1); issue(2); issue(3);

    const uint32_t arow = (uint32_t)(wm * 64 + (lane & 15));
    const uint32_t brow = (uint32_t)(wn * 64 + (lane & 15));
    const uint32_t khalf = ((uint32_t)lane >> 4) << 4;

    for (int c = 0; c < NC; c++) {
        asm volatile("cp.async.wait_group 3;" ::: "memory");
        __syncthreads();
        const uint32_t st = sb + (uint32_t)(c % PIPE) * STG;
#pragma unroll
        for (int ks = 0; ks < 4; ks++) {
            const uint32_t col = (uint32_t)ks * 32 + khalf;
            uint32_t ah[4][4];
#pragma unroll
            for (int mt = 0; mt < 4; mt++)
                ldsm4(ah[mt], st + OF_A + SW((arow + mt * 16) * 128 + col));
#pragma unroll
            for (int ntp = 0; ntp < 4; ntp++) {
                uint32_t rh[4];
                ldsm4(rh, st + OF_B + SW((brow + ntp * 16) * 128 + col));
                uint32_t b0[2] = { rh[0], rh[2] }, b1[2] = { rh[1], rh[3] };
#pragma unroll
                for (int mt = 0; mt < 4; mt++) {
                    hmma(acc[mt][2 * ntp],     ah[mt], b0);
                    hmma(acc[mt][2 * ntp + 1], ah[mt], b1);
                }
            }
        }
        __syncthreads();
        issue(c + 4);
    }

    const int row0 = bm + wm * 64 + (lane >> 2);
    const int col0 = bn + wn * 64 + ((lane & 3) << 1);
#pragma unroll
    for (int mt = 0; mt < 4; mt++) {
#pragma unroll
        for (int nt = 0; nt < 8; nt++) {
            const int r0 = row0 + mt * 16;
            const int cc = col0 + nt * 8;
            if (EPI == 1) {
                float2 v0 = make_float2(acc[mt][nt][0], acc[mt][nt][1]);
                float2 v1 = make_float2(acc[mt][nt][2], acc[mt][nt][3]);
                const float2 ra = *(const float2*)(R + (size_t)r0 * N + cc);
                const float2 rb = *(const float2*)(R + (size_t)(r0 + 8) * N + cc);
                v0.x += ra.x; v0.y += ra.y;
                v1.x += rb.x; v1.y += rb.y;
                *(float2*)(Cf + (size_t)r0 * N + cc) = v0;
                *(float2*)(Cf + (size_t)(r0 + 8) * N + cc) = v1;
            } else if (EPI == 2) {
#pragma unroll
                for (int half = 0; half < 2; half++) {
                    float v0 = acc[mt][nt][2 * half + 0];
                    float v1 = acc[mt][nt][2 * half + 1];
                    v0 = fmaxf(v0, 0.f); v0 *= v0;
                    v1 = fmaxf(v1, 0.f); v1 *= v1;
                    *(uint32_t*)(Ch + (size_t)(r0 + 8 * half) * N + cc) = packh(v0, v1);
                }
            } else { // EPI == 3: fused RoPE scatter
#pragma unroll
                for (int half = 0; half < 2; half++) {
                    const int row = r0 + 8 * half;
                    const int b = row >> 11;       // / S_
                    const int s = row & (S_ - 1);
                    const float x0 = acc[mt][nt][2 * half + 0];
                    const float x1 = acc[mt][nt][2 * half + 1];
                    const int d = cc & 127;
                    if (cc < D_) {
                        const int h = cc >> 7;
                        const float cs = rcos[s * HD_ + d];
                        const float sn = rsin[s * HD_ + d];
                        const float q0 = x0 * cs - x1 * sn;
                        const float q1 = x1 * cs + x0 * sn;
                        uint32_t hp, lp;
                        split2h(q0, q1, hp, lp);
                        const size_t o = (((size_t)(b * QC_ + h)) * S_ + s) * HD_ + d;
                        *(uint32_t*)(oqh + o) = hp;
                        *(uint32_t*)(oql + o) = lp;
                    } else if (cc < D_ + 512) {
                        const int h = (cc - D_) >> 7;
                        const float cs = rcos[s * HD_ + d];
                        const float sn = rsin[s * HD_ + d];
                        const float ksc = 0.08838834764831845f * 1.4426950408889634f;
                        const float k0 = (x0 * cs - x1 * sn) * ksc;
                        const float k1 = (x1 * cs + x0 * sn) * ksc;
                        const size_t o = (((size_t)(b * KVC_ + h)) * S_ + s) * HD_ + d;
                        *(uint32_t*)(okk + o) = packh(k0, k1);
                    } else {
                        const int h = (cc - D_ - 512) >> 7;
                        const size_t o = (((size_t)(b * KVC_ + h)) * S_ + s) * HD_ + d;
                        *(uint32_t*)(ovv + o) = packh(x0, x1);
                    }
                }
            }
        }
    }
}

// ---------------- HMMA flash attention (fp16, Q/P split 2-pass) ----------
#define FL_QH 0
#define FL_QL 16384
#define FL_ST(s) (32768 + (s) * 32768)
#define FL_K 0
#define FL_V 16384
#define FLASH_SMEM (32768 + 2 * 32768)

__device__ __forceinline__ uint32_t floff(uint32_t r, uint32_t hb) {
    return (hb >> 7) * 8192 + r * 128 + ((hb & 127) ^ ((r & 7) << 4));
}

__global__ __launch_bounds__(128) void flash_kernel(
    const __half* __restrict__ qh, const __half* __restrict__ ql,
    const __half* __restrict__ kk, const __half* __restrict__ vv,
    __half* __restrict__ oat)
{
    extern __shared__ char smem[];
    const uint32_t sb = smem_u32(smem);
    const int tid = threadIdx.x;
    const int w = tid >> 5, lane = tid & 31;
    const int qt = (int)(gridDim.x - 1 - blockIdx.x);
    const int h = blockIdx.y;
    const int b = blockIdx.z;
    const int kvh = h & 3;

    const __half* qbh = qh + (((size_t)(b * QC_ + h)) * S_ + qt * 64) * HD_;
    const __half* qbl = ql + (((size_t)(b * QC_ + h)) * S_ + qt * 64) * HD_;
    const size_t kvbase = ((size_t)(b * KVC_ + kvh)) * S_ * HD_;

    auto ldtile = [&](uint32_t dst, const __half* src) {
#pragma unroll
        for (int i = 0; i < 8; i++) {
            const int idx = tid + 128 * i;
            const uint32_t r = (uint32_t)idx >> 4;
            const uint32_t hb = ((uint32_t)idx & 15) << 4;
            cpa(dst + floff(r, hb), (const char*)src + (size_t)r * 256 + hb);
        }
    };
    auto issue = [&](int kt) {
        if (kt <= qt) {
            const uint32_t st = sb + FL_ST(kt & 1);
            ldtile(st + FL_K, kk + kvbase + (size_t)kt * 64 * HD_);
            ldtile(st + FL_V, vv + kvbase + (size_t)kt * 64 * HD_);
        }
        asm volatile("cp.async.commit_group;");
    };

    ldtile(sb + FL_QH, qbh);
    ldtile(sb + FL_QL, qbl);
    issue(0);
    issue(1);

    float o[16][4];
#pragma unroll
    for (int i = 0; i < 16; i++)
#pragma unroll
        for (int j = 0; j < 4; j++) o[i][j] = 0.f;
    float m_l = -1e30f, m_h = -1e30f, l_l = 0.f, l_h = 0.f;

    const uint32_t arow = (uint32_t)(w * 16 + (lane & 15));
    const uint32_t khalf = ((uint32_t)lane >> 4) << 4;
    const int rl = lane >> 2;
    const int cq = (lane & 3) << 1;

    for (int kt = 0; kt <= qt; kt++) {
        asm volatile("cp.async.wait_group 1;" ::: "memory");
        __syncthreads();
        const uint32_t st = sb + FL_ST(kt & 1);

        float sacc[8][4];
#pragma unroll
        for (int i = 0; i < 8; i++)
#pragma unroll
            for (int j = 0; j < 4; j++) sacc[i][j] = 0.f;

#pragma unroll
        for (int ks = 0; ks < 8; ks++) {
            const uint32_t hb = (uint32_t)ks * 32 + khalf;
            uint32_t aqh[4], aql[4];
            ldsm4(aqh, sb + FL_QH + floff(arow, hb));
            ldsm4(aql, sb + FL_QL + floff(arow, hb));
#pragma unroll
            for (int ntp = 0; ntp < 4; ntp++) {
                const uint32_t krow = (uint32_t)(ntp * 16) + (lane & 15);
                uint32_t rh[4];
                ldsm4(rh, st + FL_K + floff(krow, hb));
                uint32_t b0[2] = { rh[0], rh[2] }, b1[2] = { rh[1], rh[3] };
                hmma(sacc[2 * ntp],     aqh, b0);
                hmma(sacc[2 * ntp],     aql, b0);
                hmma(sacc[2 * ntp + 1], aqh, b1);
                hmma(sacc[2 * ntp + 1], aql, b1);
            }
        }

        if (kt == qt) {
            const int rowl = w * 16 + rl;
            const int rowh = rowl + 8;
#pragma unroll
            for (int nt = 0; nt < 8; nt++) {
                const int c0 = nt * 8 + cq, c1 = c0 + 1;
                if (c0 > rowl) sacc[nt][0] = -1e30f;
                if (c1 > rowl) sacc[nt][1] = -1e30f;
                if (c0 > rowh) sacc[nt][2] = -1e30f;
                if (c1 > rowh) sacc[nt][3] = -1e30f;
            }
        }

        float mx_l = -1e30f, mx_h = -1e30f;
#pragma unroll
        for (int nt = 0; nt < 8; nt++) {
            mx_l = fmaxf(mx_l, fmaxf(sacc[nt][0], sacc[nt][1]));
            mx_h = fmaxf(mx_h, fmaxf(sacc[nt][2], sacc[nt][3]));
        }
#pragma unroll
        for (int sh = 1; sh < 4; sh <<= 1) {
            mx_l = fmaxf(mx_l, __shfl_xor_sync(0xffffffffu, mx_l, sh));
            mx_h = fmaxf(mx_h, __shfl_xor_sync(0xffffffffu, mx_h, sh));
        }
        const float mn_l = fmaxf(m_l, mx_l);
        const float mn_h = fmaxf(m_h, mx_h);
        const float sc_l = ex2(m_l - mn_l);
        const float sc_h = ex2(m_h - mn_h);
        m_l = mn_l;
        m_h = mn_h;

        float sum_l = 0.f, sum_h = 0.f;
#pragma unroll
        for (int nt = 0; nt < 8; nt++) {
            sacc[nt][0] = ex2(sacc[nt][0] - mn_l);
            sacc[nt][1] = ex2(sacc[nt][1] - mn_l);
            sacc[nt][2] = ex2(sacc[nt][2] - mn_h);
            sacc[nt][3] = ex2(sacc[nt][3] - mn_h);
            sum_l += sacc[nt][0] + sacc[nt][1];
            sum_h += sacc[nt][2] + sacc[nt][3];
        }
#pragma unroll
        for (int sh = 1; sh < 4; sh <<= 1) {
            sum_l += __shfl_xor_sync(0xffffffffu, sum_l, sh);
            sum_h += __shfl_xor_sync(0xffffffffu, sum_h, sh);
        }
        l_l = l_l * sc_l + sum_l;
        l_h = l_h * sc_h + sum_h;
#pragma unroll
        for (int i = 0; i < 16; i++) {
            o[i][0] *= sc_l; o[i][1] *= sc_l;
            o[i][2] *= sc_h; o[i][3] *= sc_h;
        }

        uint32_t ph[4][4], pl[4][4];
#pragma unroll
        for (int kf = 0; kf < 4; kf++) {
            split2h(sacc[2 * kf][0], sacc[2 * kf][1], ph[kf][0], pl[kf][0]);
            split2h(sacc[2 * kf][2], sacc[2 * kf][3], ph[kf][1], pl[kf][1]);
            split2h(sacc[2 * kf + 1][0], sacc[2 * kf + 1][1], ph[kf][2], pl[kf][2]);
            split2h(sacc[2 * kf + 1][2], sacc[2 * kf + 1][3], ph[kf][3], pl[kf][3]);
        }

#pragma unroll
        for (int kf = 0; kf < 4; kf++) {
            const uint32_t vrow = (uint32_t)(kf * 16) + (lane & 7) + (((uint32_t)lane >> 3) & 1) * 8;
#pragma unroll
            for (int np = 0; np < 8; np++) {
                const uint32_t hb = (uint32_t)np * 32 + khalf;
                uint32_t rv[4];
                ldsm4t(rv, st + FL_V + floff(vrow, hb));
                uint32_t b0[2] = { rv[0], rv[1] }, b1[2] = { rv[2], rv[3] };
                hmma(o[2 * np],     ph[kf], b0);
                hmma(o[2 * np],     pl[kf], b0);
                hmma(o[2 * np + 1], ph[kf], b1);
                hmma(o[2 * np + 1], pl[kf], b1);
            }
        }

        __syncthreads();
        issue(kt + 2);
    }

    const float inv_l = 1.f / l_l;
    const float inv_h = 1.f / l_h;
    const int grl = qt * 64 + w * 16 + rl;
    const int grh = grl + 8;
    const size_t basel = ((size_t)b * S_ + grl) * D_ + h * HD_;
    const size_t baseh = ((size_t)b * S_ + grh) * D_ + h * HD_;
#pragma unroll
    for (int nt = 0; nt < 16; nt++) {
        const int hd0 = nt * 8 + cq;
        *(uint32_t*)(oat + basel + hd0) = packh(o[nt][0] * inv_l, o[nt][1] * inv_l);
        *(uint32_t*)(oat + baseh + hd0) = packh(o[nt][2] * inv_h, o[nt][3] * inv_h);
    }
}

// ---------------- launcher ----------------
extern "C" void kernel_launch(void* const* d_in, const int* in_sizes, int n_in,
                              void* d_out, int out_size)
{
    (void)in_sizes; (void)n_in; (void)out_size;
    const float* x    = (const float*)d_in[0];
    const float* rsin = (const float*)d_in[2];
    const float* rcos = (const float*)d_in[3];
    const float* wqkv = (const float*)d_in[4];
    const float* wo   = (const float*)d_in[5];
    const float* n1   = (const float*)d_in[6];
    const float* n2   = (const float*)d_in[7];
    const float* wk   = (const float*)d_in[8];
    const float* wv   = (const float*)d_in[9];
    float* out = (float*)d_out;

    float* p_x1;
    __half *p_qh, *p_ql, *p_k, *p_v, *p_xn, *p_at, *p_h;
    __half *p_wqkv, *p_wo, *p_wk, *p_wv;
    cudaGetSymbolAddress((void**)&p_x1, g_x1);
    cudaGetSymbolAddress((void**)&p_qh, g_qh);
    cudaGetSymbolAddress((void**)&p_ql, g_ql);
    cudaGetSymbolAddress((void**)&p_k, g_k);
    cudaGetSymbolAddress((void**)&p_v, g_v);
    cudaGetSymbolAddress((void**)&p_xn, g_xn);
    cudaGetSymbolAddress((void**)&p_at, g_at);
    cudaGetSymbolAddress((void**)&p_h, g_h);
    cudaGetSymbolAddress((void**)&p_wqkv, g_wqkv);
    cudaGetSymbolAddress((void**)&p_wo, g_wo);
    cudaGetSymbolAddress((void**)&p_wk, g_wk);
    cudaGetSymbolAddress((void**)&p_wv, g_wv);

    cudaFuncSetAttribute(flash_kernel, cudaFuncAttributeMaxDynamicSharedMemorySize, FLASH_SMEM);
    cudaFuncSetAttribute(mma_gemm<1>, cudaFuncAttributeMaxDynamicSharedMemorySize, GEMM_SMEM);
    cudaFuncSetAttribute(mma_gemm<2>, cudaFuncAttributeMaxDynamicSharedMemorySize, GEMM_SMEM);
    cudaFuncSetAttribute(mma_gemm<3>, cudaFuncAttributeMaxDynamicSharedMemorySize, GEMM_SMEM);

    const dim3 tb(32, 8);
    wcvt_kernel<<<dim3(QKVN / 32, D_ / 32), tb>>>(wqkv, p_wqkv, D_, QKVN);
    wcvt_kernel<<<dim3(D_ / 32, D_ / 32), tb>>>(wo, p_wo, D_, D_);
    wcvt_kernel<<<dim3(FF_ / 32, D_ / 32), tb>>>(wk, p_wk, D_, FF_);
    wcvt_kernel<<<dim3(D_ / 32, FF_ / 32), tb>>>(wv, p_wv, FF_, D_);

    // x1 = x + attn(rmsnorm(x))
    rmsnorm_h_kernel<<<M_, 256>>>(x, n1, p_xn);
    mma_gemm<3><<<dim3(QKVN / 256, M_ / 128), 256, GEMM_SMEM>>>(
        p_xn, p_wqkv, nullptr, nullptr, nullptr, rsin, rcos,
        p_qh, p_ql, p_k, p_v, QKVN, D_);
    flash_kernel<<<dim3(S_ / 64, QC_, B_), 128, FLASH_SMEM>>>(
        p_qh, p_ql, p_k, p_v, p_at);
    mma_gemm<1><<<dim3(D_ / 256, M_ / 128), 256, GEMM_SMEM>>>(
        p_at, p_wo, x, p_x1, nullptr, nullptr, nullptr,
        nullptr, nullptr, nullptr, nullptr, D_, D_);

    // out = x1 + ffn(rmsnorm(x1))
    rmsnorm_h_kernel<<<M_, 256>>>(p_x1, n2, p_xn);
    mma_gemm<2><<<dim3(FF_ / 256, M_ / 128), 256, GEMM_SMEM>>>(
        p_xn, p_wk, nullptr, nullptr, p_h, nullptr, nullptr,
        nullptr, nullptr, nullptr, nullptr, FF_, D_);
    mma_gemm<1><<<dim3(D_ / 256, M_ / 128), 256, GEMM_SMEM>>>(
        p_h, p_wv, p_x1, out, nullptr, nullptr, nullptr,
        nullptr, nullptr, nullptr, nullptr, D_, FF_);
}

// round 7
// speedup vs baseline: 6.5905x; 1.0194x over previous
#include <cuda_runtime.h>
#include <cuda_fp16.h>
#include <cstdint>
#include <cstddef>

#define B_   2
#define S_   2048
#define D_   2048
#define QC_  16
#define KVC_ 4
#define HD_  128
#define FF_  8192
#define M_   (B_ * S_)             // 4096
#define QKVN (D_ + 2 * KVC_ * HD_) // 3072

// ---------------- scratch ----------------
__device__ float g_x1  [(size_t)M_ * D_];
__device__ __half g_qh [(size_t)B_ * QC_  * S_ * HD_];
__device__ __half g_ql [(size_t)B_ * QC_  * S_ * HD_];
__device__ __half g_k  [(size_t)B_ * KVC_ * S_ * HD_];
__device__ __half g_v  [(size_t)B_ * KVC_ * S_ * HD_];
__device__ __half g_xn [(size_t)M_ * D_];
__device__ __half g_at [(size_t)M_ * D_];
__device__ __half g_h  [(size_t)M_ * FF_];
__device__ __half g_wqkv [(size_t)D_ * QKVN];
__device__ __half g_wo   [(size_t)D_ * D_];
__device__ __half g_wk   [(size_t)D_ * FF_];
__device__ __half g_wv   [(size_t)FF_ * D_];

// ---------------- helpers ----------------
__device__ __forceinline__ uint32_t smem_u32(const void* p) {
    uint32_t a;
    asm("{ .reg .u64 t; cvta.to.shared.u64 t, %1; cvt.u32.u64 %0, t; }" : "=r"(a) : "l"(p));
    return a;
}
__device__ __forceinline__ void split2h(float x, float y, uint32_t& hi, uint32_t& lo) {
    __half2 h = __floats2half2_rn(x, y);
    const float hx = __half2float(__low2half(h));
    const float hy = __half2float(__high2half(h));
    __half2 l = __floats2half2_rn(x - hx, y - hy);
    hi = *(uint32_t*)&h;
    lo = *(uint32_t*)&l;
}
__device__ __forceinline__ uint32_t packh(float x, float y) {
    __half2 h = __floats2half2_rn(x, y);
    return *(uint32_t*)&h;
}
__device__ __forceinline__ float ex2(float x) {
    float y;
    asm("ex2.approx.f32 %0, %1;" : "=f"(y) : "f"(x));
    return y;
}

__device__ __forceinline__ void ldsm4(uint32_t* r, uint32_t addr) {
    asm volatile("ldmatrix.sync.aligned.m8n8.x4.shared.b16 {%0,%1,%2,%3},[%4];"
                 : "=r"(r[0]), "=r"(r[1]), "=r"(r[2]), "=r"(r[3]) : "r"(addr));
}
__device__ __forceinline__ void ldsm4t(uint32_t* r, uint32_t addr) {
    asm volatile("ldmatrix.sync.aligned.m8n8.x4.trans.shared.b16 {%0,%1,%2,%3},[%4];"
                 : "=r"(r[0]), "=r"(r[1]), "=r"(r[2]), "=r"(r[3]) : "r"(addr));
}
__device__ __forceinline__ void hmma(float* c, const uint32_t* a, const uint32_t* b) {
    asm volatile("mma.sync.aligned.m16n8k16.row.col.f32.f16.f16.f32 "
                 "{%0,%1,%2,%3},{%4,%5,%6,%7},{%8,%9},{%0,%1,%2,%3};"
                 : "+f"(c[0]), "+f"(c[1]), "+f"(c[2]), "+f"(c[3])
                 : "r"(a[0]), "r"(a[1]), "r"(a[2]), "r"(a[3]), "r"(b[0]), "r"(b[1]));
}
__device__ __forceinline__ void cpa(uint32_t dst, const void* src) {
    asm volatile("cp.async.cg.shared.global [%0],[%1],16;" :: "r"(dst), "l"(src));
}

// ---------------- RMSNorm -> fp16 ----------------
__global__ __launch_bounds__(256) void rmsnorm_h_kernel(
    const float* __restrict__ x, const float* __restrict__ w,
    __half* __restrict__ o)
{
    const int row = blockIdx.x;
    const int tid = threadIdx.x;
    const float4* xr = (const float4*)(x + (size_t)row * D_);
    float4 vals[2];
    float ss = 0.f;
#pragma unroll
    for (int i = 0; i < 2; i++) {
        float4 v = xr[tid + 256 * i];
        vals[i] = v;
        ss += v.x * v.x + v.y * v.y + v.z * v.z + v.w * v.w;
    }
#pragma unroll
    for (int sh = 16; sh > 0; sh >>= 1) ss += __shfl_xor_sync(0xffffffffu, ss, sh);
    __shared__ float red[8];
    if ((tid & 31) == 0) red[tid >> 5] = ss;
    __syncthreads();
    float tot = 0.f;
#pragma unroll
    for (int i = 0; i < 8; i++) tot += red[i];
    const float rs = rsqrtf(tot * (1.f / (float)D_) + 1e-5f);
    const float4* w4 = (const float4*)w;
#pragma unroll
    for (int i = 0; i < 2; i++) {
        float4 v = vals[i], ww = w4[tid + 256 * i];
        const size_t base = (size_t)row * D_ + (tid + 256 * i) * 4;
        *(uint32_t*)(o + base)     = packh(v.x * rs * ww.x, v.y * rs * ww.y);
        *(uint32_t*)(o + base + 2) = packh(v.z * rs * ww.z, v.w * rs * ww.w);
    }
}

// ---------------- weight fp16 convert (streaming, no transpose) ----------
__global__ __launch_bounds__(256) void wcvt_kernel(
    const float* __restrict__ W, __half* __restrict__ out)
{
    const size_t i = ((size_t)blockIdx.x * 256 + threadIdx.x) * 8;
    const float4 a = *(const float4*)(W + i);
    const float4 b = *(const float4*)(W + i + 4);
    uint4 r;
    r.x = packh(a.x, a.y);
    r.y = packh(a.z, a.w);
    r.z = packh(b.x, b.y);
    r.w = packh(b.z, b.w);
    *(uint4*)(out + i) = r;
}

// ---------------- HMMA GEMM: CTA 128x256, warp 64x64, fp16, B in [K,N] ----------
// EPI 1: Cf = acc + R ; EPI 2: Ch = half(relu(acc)^2) ;
// EPI 3: fused RoPE scatter to q(hi/lo)/k/v
#define PIPE 4
#define STG  49152
#define OF_A 0
#define OF_B 16384
#define GEMM_SMEM (PIPE * STG)

// B smem: [4 nblks of 128B][64 k-rows][128B], swizzled
__device__ __forceinline__ uint32_t boff(uint32_t r, uint32_t nb) {
    return (nb >> 7) * 8192 + r * 128 + ((nb & 127) ^ ((r & 7) << 4));
}

template <int EPI>
__global__ __launch_bounds__(256) void mma_gemm(
    const __half* __restrict__ A, const __half* __restrict__ Bw,
    const float* __restrict__ R, float* __restrict__ Cf,
    __half* __restrict__ Ch,
    const float* __restrict__ rsin, const float* __restrict__ rcos,
    __half* __restrict__ oqh, __half* __restrict__ oql,
    __half* __restrict__ okk, __half* __restrict__ ovv,
    int N, int K)
{
    extern __shared__ char smem[];
    const uint32_t sb = smem_u32(smem);
    const int tid = threadIdx.x;
    const int wid = tid >> 5, lane = tid & 31;
    const int wm = wid & 1, wn = wid >> 1;
    const int bm = blockIdx.y * 128, bn = blockIdx.x * 256;
    const int NC = K >> 6;

    float acc[4][8][4];
#pragma unroll
    for (int i = 0; i < 4; i++)
#pragma unroll
        for (int j = 0; j < 8; j++)
#pragma unroll
            for (int q = 0; q < 4; q++) acc[i][j][q] = 0.f;

    auto issue = [&](int c) {
        if (c < NC) {
            const int kc = c << 6;
            const uint32_t st = sb + (uint32_t)(c % PIPE) * STG;
            const char* pa = (const char*)(A + (size_t)bm * K + kc);
            const char* pb = (const char*)(Bw + (size_t)kc * N + bn);
            // A: [128 m-rows][64 k-cols = 128B]
#pragma unroll
            for (int i = 0; i < 4; i++) {
                const int idx = tid + 256 * i;
                const int r = idx >> 3;
                const uint32_t ch = (idx & 7) << 4;
                const uint32_t so = (uint32_t)(r * 128) + (ch ^ (((uint32_t)r & 7) << 4));
                cpa(st + OF_A + so, pa + (size_t)r * (K * 2) + ch);
            }
            // B: [64 k-rows][256 n-cols = 512B]
#pragma unroll
            for (int i = 0; i < 8; i++) {
                const int idx = tid + 256 * i;
                const int r = idx >> 5;
                const uint32_t cb = (idx & 31) << 4;
                cpa(st + OF_B + boff(r, cb), pb + (size_t)r * (N * 2) + cb);
            }
        }
        asm volatile("cp.async.commit_group;");
    };

    issue(0); issue(1); issue(2); issue(3);

    const uint32_t arow = (uint32_t)(wm * 64 + (lane & 15));
    const uint32_t khalf = ((uint32_t)lane >> 4) << 4;
    const uint32_t brow_b = (uint32_t)((lane & 7) + ((lane >> 3) & 1) * 8);

    for (int c = 0; c < NC; c++) {
        asm volatile("cp.async.wait_group 3;" ::: "memory");
        __syncthreads();
        const uint32_t st = sb + (uint32_t)(c % PIPE) * STG;
#pragma unroll
        for (int ks = 0; ks < 4; ks++) {
            const uint32_t acol = (uint32_t)ks * 32 + khalf;
            uint32_t ah[4][4];
#pragma unroll
            for (int mt = 0; mt < 4; mt++) {
                const uint32_t r = arow + mt * 16;
                ldsm4(ah[mt], st + OF_A + r * 128 + (acol ^ ((r & 7) << 4)));
            }
            const uint32_t vrow = (uint32_t)ks * 16 + brow_b;
#pragma unroll
            for (int np = 0; np < 4; np++) {
                const uint32_t nb = (uint32_t)(wn * 128 + np * 32) + khalf;
                uint32_t rh[4];
                ldsm4t(rh, st + OF_B + boff(vrow, nb));
                uint32_t b0[2] = { rh[0], rh[1] }, b1[2] = { rh[2], rh[3] };
#pragma unroll
                for (int mt = 0; mt < 4; mt++) {
                    hmma(acc[mt][2 * np],     ah[mt], b0);
                    hmma(acc[mt][2 * np + 1], ah[mt], b1);
                }
            }
        }
        __syncthreads();
        issue(c + 4);
    }

    const int row0 = bm + wm * 64 + (lane >> 2);
    const int col0 = bn + wn * 64 + ((lane & 3) << 1);
#pragma unroll
    for (int mt = 0; mt < 4; mt++) {
#pragma unroll
        for (int nt = 0; nt < 8; nt++) {
            const int r0 = row0 + mt * 16;
            const int cc = col0 + nt * 8;
            if (EPI == 1) {
                float2 v0 = make_float2(acc[mt][nt][0], acc[mt][nt][1]);
                float2 v1 = make_float2(acc[mt][nt][2], acc[mt][nt][3]);
                const float2 ra = *(const float2*)(R + (size_t)r0 * N + cc);
                const float2 rb = *(const float2*)(R + (size_t)(r0 + 8) * N + cc);
                v0.x += ra.x; v0.y += ra.y;
                v1.x += rb.x; v1.y += rb.y;
                *(float2*)(Cf + (size_t)r0 * N + cc) = v0;
                *(float2*)(Cf + (size_t)(r0 + 8) * N + cc) = v1;
            } else if (EPI == 2) {
#pragma unroll
                for (int half = 0; half < 2; half++) {
                    float v0 = acc[mt][nt][2 * half + 0];
                    float v1 = acc[mt][nt][2 * half + 1];
                    v0 = fmaxf(v0, 0.f); v0 *= v0;
                    v1 = fmaxf(v1, 0.f); v1 *= v1;
                    *(uint32_t*)(Ch + (size_t)(r0 + 8 * half) * N + cc) = packh(v0, v1);
                }
            } else { // EPI == 3: fused RoPE scatter
#pragma unroll
                for (int half = 0; half < 2; half++) {
                    const int row = r0 + 8 * half;
                    const int b = row >> 11;
                    const int s = row & (S_ - 1);
                    const float x0 = acc[mt][nt][2 * half + 0];
                    const float x1 = acc[mt][nt][2 * half + 1];
                    const int d = cc & 127;
                    if (cc < D_) {
                        const int h = cc >> 7;
                        const float cs = rcos[s * HD_ + d];
                        const float sn = rsin[s * HD_ + d];
                        const float q0 = x0 * cs - x1 * sn;
                        const float q1 = x1 * cs + x0 * sn;
                        uint32_t hp, lp;
                        split2h(q0, q1, hp, lp);
                        const size_t o = (((size_t)(b * QC_ + h)) * S_ + s) * HD_ + d;
                        *(uint32_t*)(oqh + o) = hp;
                        *(uint32_t*)(oql + o) = lp;
                    } else if (cc < D_ + 512) {
                        const int h = (cc - D_) >> 7;
                        const float cs = rcos[s * HD_ + d];
                        const float sn = rsin[s * HD_ + d];
                        const float ksc = 0.08838834764831845f * 1.4426950408889634f;
                        const float k0 = (x0 * cs - x1 * sn) * ksc;
                        const float k1 = (x1 * cs + x0 * sn) * ksc;
                        const size_t o = (((size_t)(b * KVC_ + h)) * S_ + s) * HD_ + d;
                        *(uint32_t*)(okk + o) = packh(k0, k1);
                    } else {
                        const int h = (cc - D_ - 512) >> 7;
                        const size_t o = (((size_t)(b * KVC_ + h)) * S_ + s) * HD_ + d;
                        *(uint32_t*)(ovv + o) = packh(x0, x1);
                    }
                }
            }
        }
    }
}

// ---------------- HMMA flash attention (Q 2-pass, P single-pass) ----------
#define FL_QH 0
#define FL_QL 16384
#define FL_ST(s) (32768 + (s) * 32768)
#define FL_K 0
#define FL_V 16384
#define FLASH_SMEM (32768 + 2 * 32768)

__device__ __forceinline__ uint32_t floff(uint32_t r, uint32_t hb) {
    return (hb >> 7) * 8192 + r * 128 + ((hb & 127) ^ ((r & 7) << 4));
}

__global__ __launch_bounds__(128) void flash_kernel(
    const __half* __restrict__ qh, const __half* __restrict__ ql,
    const __half* __restrict__ kk, const __half* __restrict__ vv,
    __half* __restrict__ oat)
{
    extern __shared__ char smem[];
    const uint32_t sb = smem_u32(smem);
    const int tid = threadIdx.x;
    const int w = tid >> 5, lane = tid & 31;
    const int qt = (int)(gridDim.x - 1 - blockIdx.x);
    const int h = blockIdx.y;
    const int b = blockIdx.z;
    const int kvh = h & 3;

    const __half* qbh = qh + (((size_t)(b * QC_ + h)) * S_ + qt * 64) * HD_;
    const __half* qbl = ql + (((size_t)(b * QC_ + h)) * S_ + qt * 64) * HD_;
    const size_t kvbase = ((size_t)(b * KVC_ + kvh)) * S_ * HD_;

    auto ldtile = [&](uint32_t dst, const __half* src) {
#pragma unroll
        for (int i = 0; i < 8; i++) {
            const int idx = tid + 128 * i;
            const uint32_t r = (uint32_t)idx >> 4;
            const uint32_t hb = ((uint32_t)idx & 15) << 4;
            cpa(dst + floff(r, hb), (const char*)src + (size_t)r * 256 + hb);
        }
    };
    auto issue = [&](int kt) {
        if (kt <= qt) {
            const uint32_t st = sb + FL_ST(kt & 1);
            ldtile(st + FL_K, kk + kvbase + (size_t)kt * 64 * HD_);
            ldtile(st + FL_V, vv + kvbase + (size_t)kt * 64 * HD_);
        }
        asm volatile("cp.async.commit_group;");
    };

    ldtile(sb + FL_QH, qbh);
    ldtile(sb + FL_QL, qbl);
    issue(0);
    issue(1);

    float o[16][4];
#pragma unroll
    for (int i = 0; i < 16; i++)
#pragma unroll
        for (int j = 0; j < 4; j++) o[i][j] = 0.f;
    float m_l = -1e30f, m_h = -1e30f, l_l = 0.f, l_h = 0.f;

    const uint32_t arow = (uint32_t)(w * 16 + (lane & 15));
    const uint32_t khalf = ((uint32_t)lane >> 4) << 4;
    const int rl = lane >> 2;
    const int cq = (lane & 3) << 1;

    for (int kt = 0; kt <= qt; kt++) {
        asm volatile("cp.async.wait_group 1;" ::: "memory");
        __syncthreads();
        const uint32_t st = sb + FL_ST(kt & 1);

        float sacc[8][4];
#pragma unroll
        for (int i = 0; i < 8; i++)
#pragma unroll
            for (int j = 0; j < 4; j++) sacc[i][j] = 0.f;

#pragma unroll
        for (int ks = 0; ks < 8; ks++) {
            const uint32_t hb = (uint32_t)ks * 32 + khalf;
            uint32_t aqh[4], aql[4];
            ldsm4(aqh, sb + FL_QH + floff(arow, hb));
            ldsm4(aql, sb + FL_QL + floff(arow, hb));
#pragma unroll
            for (int ntp = 0; ntp < 4; ntp++) {
                const uint32_t krow = (uint32_t)(ntp * 16) + (lane & 15);
                uint32_t rh[4];
                ldsm4(rh, st + FL_K + floff(krow, hb));
                uint32_t b0[2] = { rh[0], rh[2] }, b1[2] = { rh[1], rh[3] };
                hmma(sacc[2 * ntp],     aqh, b0);
                hmma(sacc[2 * ntp],     aql, b0);
                hmma(sacc[2 * ntp + 1], aqh, b1);
                hmma(sacc[2 * ntp + 1], aql, b1);
            }
        }

        if (kt == qt) {
            const int rowl = w * 16 + rl;
            const int rowh = rowl + 8;
#pragma unroll
            for (int nt = 0; nt < 8; nt++) {
                const int c0 = nt * 8 + cq, c1 = c0 + 1;
                if (c0 > rowl) sacc[nt][0] = -1e30f;
                if (c1 > rowl) sacc[nt][1] = -1e30f;
                if (c0 > rowh) sacc[nt][2] = -1e30f;
                if (c1 > rowh) sacc[nt][3] = -1e30f;
            }
        }

        float mx_l = -1e30f, mx_h = -1e30f;
#pragma unroll
        for (int nt = 0; nt < 8; nt++) {
            mx_l = fmaxf(mx_l, fmaxf(sacc[nt][0], sacc[nt][1]));
            mx_h = fmaxf(mx_h, fmaxf(sacc[nt][2], sacc[nt][3]));
        }
#pragma unroll
        for (int sh = 1; sh < 4; sh <<= 1) {
            mx_l = fmaxf(mx_l, __shfl_xor_sync(0xffffffffu, mx_l, sh));
            mx_h = fmaxf(mx_h, __shfl_xor_sync(0xffffffffu, mx_h, sh));
        }
        const float mn_l = fmaxf(m_l, mx_l);
        const float mn_h = fmaxf(m_h, mx_h);
        const float sc_l = ex2(m_l - mn_l);
        const float sc_h = ex2(m_h - mn_h);
        m_l = mn_l;
        m_h = mn_h;

        float sum_l = 0.f, sum_h = 0.f;
#pragma unroll
        for (int nt = 0; nt < 8; nt++) {
            sacc[nt][0] = ex2(sacc[nt][0] - mn_l);
            sacc[nt][1] = ex2(sacc[nt][1] - mn_l);
            sacc[nt][2] = ex2(sacc[nt][2] - mn_h);
            sacc[nt][3] = ex2(sacc[nt][3] - mn_h);
            sum_l += sacc[nt][0] + sacc[nt][1];
            sum_h += sacc[nt][2] + sacc[nt][3];
        }
#pragma unroll
        for (int sh = 1; sh < 4; sh <<= 1) {
            sum_l += __shfl_xor_sync(0xffffffffu, sum_l, sh);
            sum_h += __shfl_xor_sync(0xffffffffu, sum_h, sh);
        }
        l_l = l_l * sc_l + sum_l;
        l_h = l_h * sc_h + sum_h;
#pragma unroll
        for (int i = 0; i < 16; i++) {
            o[i][0] *= sc_l; o[i][1] *= sc_l;
            o[i][2] *= sc_h; o[i][3] *= sc_h;
        }

        // P frags: single fp16 pass
        uint32_t ph[4][4];
#pragma unroll
        for (int kf = 0; kf < 4; kf++) {
            ph[kf][0] = packh(sacc[2 * kf][0], sacc[2 * kf][1]);
            ph[kf][1] = packh(sacc[2 * kf][2], sacc[2 * kf][3]);
            ph[kf][2] = packh(sacc[2 * kf + 1][0], sacc[2 * kf + 1][1]);
            ph[kf][3] = packh(sacc[2 * kf + 1][2], sacc[2 * kf + 1][3]);
        }

#pragma unroll
        for (int kf = 0; kf < 4; kf++) {
            const uint32_t vrow = (uint32_t)(kf * 16) + (lane & 7) + (((uint32_t)lane >> 3) & 1) * 8;
#pragma unroll
            for (int np = 0; np < 8; np++) {
                const uint32_t hb = (uint32_t)np * 32 + khalf;
                uint32_t rv[4];
                ldsm4t(rv, st + FL_V + floff(vrow, hb));
                uint32_t b0[2] = { rv[0], rv[1] }, b1[2] = { rv[2], rv[3] };
                hmma(o[2 * np],     ph[kf], b0);
                hmma(o[2 * np + 1], ph[kf], b1);
            }
        }

        __syncthreads();
        issue(kt + 2);
    }

    const float inv_l = 1.f / l_l;
    const float inv_h = 1.f / l_h;
    const int grl = qt * 64 + w * 16 + rl;
    const int grh = grl + 8;
    const size_t basel = ((size_t)b * S_ + grl) * D_ + h * HD_;
    const size_t baseh = ((size_t)b * S_ + grh) * D_ + h * HD_;
#pragma unroll
    for (int nt = 0; nt < 16; nt++) {
        const int hd0 = nt * 8 + cq;
        *(uint32_t*)(oat + basel + hd0) = packh(o[nt][0] * inv_l, o[nt][1] * inv_l);
        *(uint32_t*)(oat + baseh + hd0) = packh(o[nt][2] * inv_h, o[nt][3] * inv_h);
    }
}

// ---------------- launcher ----------------
extern "C" void kernel_launch(void* const* d_in, const int* in_sizes, int n_in,
                              void* d_out, int out_size)
{
    (void)in_sizes; (void)n_in; (void)out_size;
    const float* x    = (const float*)d_in[0];
    const float* rsin = (const float*)d_in[2];
    const float* rcos = (const float*)d_in[3];
    const float* wqkv = (const float*)d_in[4];
    const float* wo   = (const float*)d_in[5];
    const float* n1   = (const float*)d_in[6];
    const float* n2   = (const float*)d_in[7];
    const float* wk   = (const float*)d_in[8];
    const float* wv   = (const float*)d_in[9];
    float* out = (float*)d_out;

    float* p_x1;
    __half *p_qh, *p_ql, *p_k, *p_v, *p_xn, *p_at, *p_h;
    __half *p_wqkv, *p_wo, *p_wk, *p_wv;
    cudaGetSymbolAddress((void**)&p_x1, g_x1);
    cudaGetSymbolAddress((void**)&p_qh, g_qh);
    cudaGetSymbolAddress((void**)&p_ql, g_ql);
    cudaGetSymbolAddress((void**)&p_k, g_k);
    cudaGetSymbolAddress((void**)&p_v, g_v);
    cudaGetSymbolAddress((void**)&p_xn, g_xn);
    cudaGetSymbolAddress((void**)&p_at, g_at);
    cudaGetSymbolAddress((void**)&p_h, g_h);
    cudaGetSymbolAddress((void**)&p_wqkv, g_wqkv);
    cudaGetSymbolAddress((void**)&p_wo, g_wo);
    cudaGetSymbolAddress((void**)&p_wk, g_wk);
    cudaGetSymbolAddress((void**)&p_wv, g_wv);

    cudaFuncSetAttribute(flash_kernel, cudaFuncAttributeMaxDynamicSharedMemorySize, FLASH_SMEM);
    cudaFuncSetAttribute(mma_gemm<1>, cudaFuncAttributeMaxDynamicSharedMemorySize, GEMM_SMEM);
    cudaFuncSetAttribute(mma_gemm<2>, cudaFuncAttributeMaxDynamicSharedMemorySize, GEMM_SMEM);
    cudaFuncSetAttribute(mma_gemm<3>, cudaFuncAttributeMaxDynamicSharedMemorySize, GEMM_SMEM);

    wcvt_kernel<<<(unsigned)((size_t)D_ * QKVN / 2048), 256>>>(wqkv, p_wqkv);
    wcvt_kernel<<<(unsigned)((size_t)D_ * D_ / 2048), 256>>>(wo, p_wo);
    wcvt_kernel<<<(unsigned)((size_t)D_ * FF_ / 2048), 256>>>(wk, p_wk);
    wcvt_kernel<<<(unsigned)((size_t)FF_ * D_ / 2048), 256>>>(wv, p_wv);

    // x1 = x + attn(rmsnorm(x))
    rmsnorm_h_kernel<<<M_, 256>>>(x, n1, p_xn);
    mma_gemm<3><<<dim3(QKVN / 256, M_ / 128), 256, GEMM_SMEM>>>(
        p_xn, p_wqkv, nullptr, nullptr, nullptr, rsin, rcos,
        p_qh, p_ql, p_k, p_v, QKVN, D_);
    flash_kernel<<<dim3(S_ / 64, QC_, B_), 128, FLASH_SMEM>>>(
        p_qh, p_ql, p_k, p_v, p_at);
    mma_gemm<1><<<dim3(D_ / 256, M_ / 128), 256, GEMM_SMEM>>>(
        p_at, p_wo, x, p_x1, nullptr, nullptr, nullptr,
        nullptr, nullptr, nullptr, nullptr, D_, D_);

    // out = x1 + ffn(rmsnorm(x1))
    rmsnorm_h_kernel<<<M_, 256>>>(p_x1, n2, p_xn);
    mma_gemm<2><<<dim3(FF_ / 256, M_ / 128), 256, GEMM_SMEM>>>(
        p_xn, p_wk, nullptr, nullptr, p_h, nullptr, nullptr,
        nullptr, nullptr, nullptr, nullptr, FF_, D_);
    mma_gemm<1><<<dim3(D_ / 256, M_ / 128), 256, GEMM_SMEM>>>(
        p_h, p_wv, p_x1, out, nullptr, nullptr, nullptr,
        nullptr, nullptr, nullptr, nullptr, D_, FF_);
}

// round 8
// speedup vs baseline: 6.6105x; 1.0030x over previous
#include <cuda_runtime.h>
#include <cuda_fp16.h>
#include <cstdint>
#include <cstddef>

#define B_   2
#define S_   2048
#define D_   2048
#define QC_  16
#define KVC_ 4
#define HD_  128
#define FF_  8192
#define M_   (B_ * S_)             // 4096
#define QKVN (D_ + 2 * KVC_ * HD_) // 3072

// ---------------- scratch ----------------
__device__ float g_x1  [(size_t)M_ * D_];
__device__ __half g_qh [(size_t)B_ * QC_  * S_ * HD_];
__device__ __half g_ql [(size_t)B_ * QC_  * S_ * HD_];
__device__ __half g_k  [(size_t)B_ * KVC_ * S_ * HD_];
__device__ __half g_v  [(size_t)B_ * KVC_ * S_ * HD_];
__device__ __half g_xn [(size_t)M_ * D_];
__device__ __half g_at [(size_t)M_ * D_];
__device__ __half g_h  [(size_t)M_ * FF_];
__device__ __half g_wqkv [(size_t)D_ * QKVN];
__device__ __half g_wo   [(size_t)D_ * D_];
__device__ __half g_wk   [(size_t)D_ * FF_];
__device__ __half g_wv   [(size_t)FF_ * D_];

// ---------------- helpers ----------------
__device__ __forceinline__ uint32_t smem_u32(const void* p) {
    uint32_t a;
    asm("{ .reg .u64 t; cvta.to.shared.u64 t, %1; cvt.u32.u64 %0, t; }" : "=r"(a) : "l"(p));
    return a;
}
__device__ __forceinline__ void split2h(float x, float y, uint32_t& hi, uint32_t& lo) {
    __half2 h = __floats2half2_rn(x, y);
    const float hx = __half2float(__low2half(h));
    const float hy = __half2float(__high2half(h));
    __half2 l = __floats2half2_rn(x - hx, y - hy);
    hi = *(uint32_t*)&h;
    lo = *(uint32_t*)&l;
}
__device__ __forceinline__ uint32_t packh(float x, float y) {
    __half2 h = __floats2half2_rn(x, y);
    return *(uint32_t*)&h;
}
__device__ __forceinline__ float ex2(float x) {
    float y;
    asm("ex2.approx.f32 %0, %1;" : "=f"(y) : "f"(x));
    return y;
}
__device__ __forceinline__ uint32_t ex2h2(uint32_t a) {
    uint32_t r;
    asm("ex2.approx.f16x2 %0, %1;" : "=r"(r) : "r"(a));
    return r;
}

__device__ __forceinline__ void ldsm4(uint32_t* r, uint32_t addr) {
    asm volatile("ldmatrix.sync.aligned.m8n8.x4.shared.b16 {%0,%1,%2,%3},[%4];"
                 : "=r"(r[0]), "=r"(r[1]), "=r"(r[2]), "=r"(r[3]) : "r"(addr));
}
__device__ __forceinline__ void ldsm4t(uint32_t* r, uint32_t addr) {
    asm volatile("ldmatrix.sync.aligned.m8n8.x4.trans.shared.b16 {%0,%1,%2,%3},[%4];"
                 : "=r"(r[0]), "=r"(r[1]), "=r"(r[2]), "=r"(r[3]) : "r"(addr));
}
__device__ __forceinline__ void hmma(float* c, const uint32_t* a, const uint32_t* b) {
    asm volatile("mma.sync.aligned.m16n8k16.row.col.f32.f16.f16.f32 "
                 "{%0,%1,%2,%3},{%4,%5,%6,%7},{%8,%9},{%0,%1,%2,%3};"
                 : "+f"(c[0]), "+f"(c[1]), "+f"(c[2]), "+f"(c[3])
                 : "r"(a[0]), "r"(a[1]), "r"(a[2]), "r"(a[3]), "r"(b[0]), "r"(b[1]));
}
__device__ __forceinline__ void cpa(uint32_t dst, const void* src) {
    asm volatile("cp.async.cg.shared.global [%0],[%1],16;" :: "r"(dst), "l"(src));
}

// ---------------- RMSNorm -> fp16 ----------------
__global__ __launch_bounds__(256) void rmsnorm_h_kernel(
    const float* __restrict__ x, const float* __restrict__ w,
    __half* __restrict__ o)
{
    const int row = blockIdx.x;
    const int tid = threadIdx.x;
    const float4* xr = (const float4*)(x + (size_t)row * D_);
    float4 vals[2];
    float ss = 0.f;
#pragma unroll
    for (int i = 0; i < 2; i++) {
        float4 v = xr[tid + 256 * i];
        vals[i] = v;
        ss += v.x * v.x + v.y * v.y + v.z * v.z + v.w * v.w;
    }
#pragma unroll
    for (int sh = 16; sh > 0; sh >>= 1) ss += __shfl_xor_sync(0xffffffffu, ss, sh);
    __shared__ float red[8];
    if ((tid & 31) == 0) red[tid >> 5] = ss;
    __syncthreads();
    float tot = 0.f;
#pragma unroll
    for (int i = 0; i < 8; i++) tot += red[i];
    const float rs = rsqrtf(tot * (1.f / (float)D_) + 1e-5f);
    const float4* w4 = (const float4*)w;
#pragma unroll
    for (int i = 0; i < 2; i++) {
        float4 v = vals[i], ww = w4[tid + 256 * i];
        const size_t base = (size_t)row * D_ + (tid + 256 * i) * 4;
        *(uint32_t*)(o + base)     = packh(v.x * rs * ww.x, v.y * rs * ww.y);
        *(uint32_t*)(o + base + 2) = packh(v.z * rs * ww.z, v.w * rs * ww.w);
    }
}

// ---------------- weight fp16 convert (streaming) ----------
__global__ __launch_bounds__(256) void wcvt_kernel(
    const float* __restrict__ W, __half* __restrict__ out)
{
    const size_t i = ((size_t)blockIdx.x * 256 + threadIdx.x) * 8;
    const float4 a = *(const float4*)(W + i);
    const float4 b = *(const float4*)(W + i + 4);
    uint4 r;
    r.x = packh(a.x, a.y);
    r.y = packh(a.z, a.w);
    r.z = packh(b.x, b.y);
    r.w = packh(b.z, b.w);
    *(uint4*)(out + i) = r;
}

// ---------------- HMMA GEMM: CTA 128x256, warp 64x64, fp16, B in [K,N] ----------
#define PIPE 4
#define STG  49152
#define OF_A 0
#define OF_B 16384
#define GEMM_SMEM (PIPE * STG)

__device__ __forceinline__ uint32_t boff(uint32_t r, uint32_t nb) {
    return (nb >> 7) * 8192 + r * 128 + ((nb & 127) ^ ((r & 7) << 4));
}

template <int EPI>
__global__ __launch_bounds__(256) void mma_gemm(
    const __half* __restrict__ A, const __half* __restrict__ Bw,
    const float* __restrict__ R, float* __restrict__ Cf,
    __half* __restrict__ Ch,
    const float* __restrict__ rsin, const float* __restrict__ rcos,
    __half* __restrict__ oqh, __half* __restrict__ oql,
    __half* __restrict__ okk, __half* __restrict__ ovv,
    int N, int K)
{
    extern __shared__ char smem[];
    const uint32_t sb = smem_u32(smem);
    const int tid = threadIdx.x;
    const int wid = tid >> 5, lane = tid & 31;
    const int wm = wid & 1, wn = wid >> 1;
    const int bm = blockIdx.y * 128, bn = blockIdx.x * 256;
    const int NC = K >> 6;

    float acc[4][8][4];
#pragma unroll
    for (int i = 0; i < 4; i++)
#pragma unroll
        for (int j = 0; j < 8; j++)
#pragma unroll
            for (int q = 0; q < 4; q++) acc[i][j][q] = 0.f;

    auto issue = [&](int c) {
        if (c < NC) {
            const int kc = c << 6;
            const uint32_t st = sb + (uint32_t)(c % PIPE) * STG;
            const char* pa = (const char*)(A + (size_t)bm * K + kc);
            const char* pb = (const char*)(Bw + (size_t)kc * N + bn);
#pragma unroll
            for (int i = 0; i < 4; i++) {
                const int idx = tid + 256 * i;
                const int r = idx >> 3;
                const uint32_t ch = (idx & 7) << 4;
                const uint32_t so = (uint32_t)(r * 128) + (ch ^ (((uint32_t)r & 7) << 4));
                cpa(st + OF_A + so, pa + (size_t)r * (K * 2) + ch);
            }
#pragma unroll
            for (int i = 0; i < 8; i++) {
                const int idx = tid + 256 * i;
                const int r = idx >> 5;
                const uint32_t cb = (idx & 31) << 4;
                cpa(st + OF_B + boff(r, cb), pb + (size_t)r * (N * 2) + cb);
            }
        }
        asm volatile("cp.async.commit_group;");
    };

    issue(0); issue(1); issue(2); issue(3);

    const uint32_t arow = (uint32_t)(wm * 64 + (lane & 15));
    const uint32_t khalf = ((uint32_t)lane >> 4) << 4;
    const uint32_t brow_b = (uint32_t)((lane & 7) + ((lane >> 3) & 1) * 8);

    for (int c = 0; c < NC; c++) {
        asm volatile("cp.async.wait_group 3;" ::: "memory");
        __syncthreads();
        const uint32_t st = sb + (uint32_t)(c % PIPE) * STG;
#pragma unroll
        for (int ks = 0; ks < 4; ks++) {
            const uint32_t acol = (uint32_t)ks * 32 + khalf;
            uint32_t ah[4][4];
#pragma unroll
            for (int mt = 0; mt < 4; mt++) {
                const uint32_t r = arow + mt * 16;
                ldsm4(ah[mt], st + OF_A + r * 128 + (acol ^ ((r & 7) << 4)));
            }
            const uint32_t vrow = (uint32_t)ks * 16 + brow_b;
#pragma unroll
            for (int np = 0; np < 4; np++) {
                const uint32_t nb = (uint32_t)(wn * 128 + np * 32) + khalf;
                uint32_t rh[4];
                ldsm4t(rh, st + OF_B + boff(vrow, nb));
                uint32_t b0[2] = { rh[0], rh[1] }, b1[2] = { rh[2], rh[3] };
#pragma unroll
                for (int mt = 0; mt < 4; mt++) {
                    hmma(acc[mt][2 * np],     ah[mt], b0);
                    hmma(acc[mt][2 * np + 1], ah[mt], b1);
                }
            }
        }
        __syncthreads();
        issue(c + 4);
    }

    const int row0 = bm + wm * 64 + (lane >> 2);
    const int col0 = bn + wn * 64 + ((lane & 3) << 1);
#pragma unroll
    for (int mt = 0; mt < 4; mt++) {
#pragma unroll
        for (int nt = 0; nt < 8; nt++) {
            const int r0 = row0 + mt * 16;
            const int cc = col0 + nt * 8;
            if (EPI == 1) {
                float2 v0 = make_float2(acc[mt][nt][0], acc[mt][nt][1]);
                float2 v1 = make_float2(acc[mt][nt][2], acc[mt][nt][3]);
                const float2 ra = *(const float2*)(R + (size_t)r0 * N + cc);
                const float2 rb = *(const float2*)(R + (size_t)(r0 + 8) * N + cc);
                v0.x += ra.x; v0.y += ra.y;
                v1.x += rb.x; v1.y += rb.y;
                *(float2*)(Cf + (size_t)r0 * N + cc) = v0;
                *(float2*)(Cf + (size_t)(r0 + 8) * N + cc) = v1;
            } else if (EPI == 2) {
#pragma unroll
                for (int half = 0; half < 2; half++) {
                    float v0 = acc[mt][nt][2 * half + 0];
                    float v1 = acc[mt][nt][2 * half + 1];
                    v0 = fmaxf(v0, 0.f); v0 *= v0;
                    v1 = fmaxf(v1, 0.f); v1 *= v1;
                    *(uint32_t*)(Ch + (size_t)(r0 + 8 * half) * N + cc) = packh(v0, v1);
                }
            } else { // EPI == 3: fused RoPE scatter
#pragma unroll
                for (int half = 0; half < 2; half++) {
                    const int row = r0 + 8 * half;
                    const int b = row >> 11;
                    const int s = row & (S_ - 1);
                    const float x0 = acc[mt][nt][2 * half + 0];
                    const float x1 = acc[mt][nt][2 * half + 1];
                    const int d = cc & 127;
                    if (cc < D_) {
                        const int h = cc >> 7;
                        const float cs = rcos[s * HD_ + d];
                        const float sn = rsin[s * HD_ + d];
                        const float q0 = x0 * cs - x1 * sn;
                        const float q1 = x1 * cs + x0 * sn;
                        uint32_t hp, lp;
                        split2h(q0, q1, hp, lp);
                        const size_t o = (((size_t)(b * QC_ + h)) * S_ + s) * HD_ + d;
                        *(uint32_t*)(oqh + o) = hp;
                        *(uint32_t*)(oql + o) = lp;
                    } else if (cc < D_ + 512) {
                        const int h = (cc - D_) >> 7;
                        const float cs = rcos[s * HD_ + d];
                        const float sn = rsin[s * HD_ + d];
                        const float ksc = 0.08838834764831845f * 1.4426950408889634f;
                        const float k0 = (x0 * cs - x1 * sn) * ksc;
                        const float k1 = (x1 * cs + x0 * sn) * ksc;
                        const size_t o = (((size_t)(b * KVC_ + h)) * S_ + s) * HD_ + d;
                        *(uint32_t*)(okk + o) = packh(k0, k1);
                    } else {
                        const int h = (cc - D_ - 512) >> 7;
                        const size_t o = (((size_t)(b * KVC_ + h)) * S_ + s) * HD_ + d;
                        *(uint32_t*)(ovv + o) = packh(x0, x1);
                    }
                }
            }
        }
    }
}

// ---------------- HMMA flash attention (Q 2-pass, f16x2 softmax, ones-MMA sums) ----
#define FL_QH 0
#define FL_QL 16384
#define FL_ST(s) (32768 + (s) * 32768)
#define FL_K 0
#define FL_V 16384
#define FLASH_SMEM (32768 + 2 * 32768)

__device__ __forceinline__ uint32_t floff(uint32_t r, uint32_t hb) {
    return (hb >> 7) * 8192 + r * 128 + ((hb & 127) ^ ((r & 7) << 4));
}

__global__ __launch_bounds__(128) void flash_kernel(
    const __half* __restrict__ qh, const __half* __restrict__ ql,
    const __half* __restrict__ kk, const __half* __restrict__ vv,
    __half* __restrict__ oat)
{
    extern __shared__ char smem[];
    const uint32_t sb = smem_u32(smem);
    const int tid = threadIdx.x;
    const int w = tid >> 5, lane = tid & 31;
    const int qt = (int)(gridDim.x - 1 - blockIdx.x);
    const int h = blockIdx.y;
    const int b = blockIdx.z;
    const int kvh = h & 3;

    const __half* qbh = qh + (((size_t)(b * QC_ + h)) * S_ + qt * 64) * HD_;
    const __half* qbl = ql + (((size_t)(b * QC_ + h)) * S_ + qt * 64) * HD_;
    const size_t kvbase = ((size_t)(b * KVC_ + kvh)) * S_ * HD_;

    auto ldtile = [&](uint32_t dst, const __half* src) {
#pragma unroll
        for (int i = 0; i < 8; i++) {
            const int idx = tid + 128 * i;
            const uint32_t r = (uint32_t)idx >> 4;
            const uint32_t hb = ((uint32_t)idx & 15) << 4;
            cpa(dst + floff(r, hb), (const char*)src + (size_t)r * 256 + hb);
        }
    };
    auto issue = [&](int kt) {
        if (kt <= qt) {
            const uint32_t st = sb + FL_ST(kt & 1);
            ldtile(st + FL_K, kk + kvbase + (size_t)kt * 64 * HD_);
            ldtile(st + FL_V, vv + kvbase + (size_t)kt * 64 * HD_);
        }
        asm volatile("cp.async.commit_group;");
    };

    ldtile(sb + FL_QH, qbh);
    ldtile(sb + FL_QL, qbl);
    issue(0);
    issue(1);

    float o[16][4];
#pragma unroll
    for (int i = 0; i < 16; i++)
#pragma unroll
        for (int j = 0; j < 4; j++) o[i][j] = 0.f;
    float m_l = -1e30f, m_h = -1e30f, l_l = 0.f, l_h = 0.f;

    const uint32_t arow = (uint32_t)(w * 16 + (lane & 15));
    const uint32_t khalf = ((uint32_t)lane >> 4) << 4;
    const int rl = lane >> 2;
    const int cq = (lane & 3) << 1;
    const uint32_t bones[2] = { 0x3C003C00u, 0x3C003C00u };

    for (int kt = 0; kt <= qt; kt++) {
        asm volatile("cp.async.wait_group 1;" ::: "memory");
        __syncthreads();
        const uint32_t st = sb + FL_ST(kt & 1);

        float sacc[8][4];
#pragma unroll
        for (int i = 0; i < 8; i++)
#pragma unroll
            for (int j = 0; j < 4; j++) sacc[i][j] = 0.f;

#pragma unroll
        for (int ks = 0; ks < 8; ks++) {
            const uint32_t hb = (uint32_t)ks * 32 + khalf;
            uint32_t aqh[4], aql[4];
            ldsm4(aqh, sb + FL_QH + floff(arow, hb));
            ldsm4(aql, sb + FL_QL + floff(arow, hb));
#pragma unroll
            for (int ntp = 0; ntp < 4; ntp++) {
                const uint32_t krow = (uint32_t)(ntp * 16) + (lane & 15);
                uint32_t rh[4];
                ldsm4(rh, st + FL_K + floff(krow, hb));
                uint32_t b0[2] = { rh[0], rh[2] }, b1[2] = { rh[1], rh[3] };
                hmma(sacc[2 * ntp],     aqh, b0);
                hmma(sacc[2 * ntp],     aql, b0);
                hmma(sacc[2 * ntp + 1], aqh, b1);
                hmma(sacc[2 * ntp + 1], aql, b1);
            }
        }

        if (kt == qt) {
            const int rowl = w * 16 + rl;
            const int rowh = rowl + 8;
#pragma unroll
            for (int nt = 0; nt < 8; nt++) {
                const int c0 = nt * 8 + cq, c1 = c0 + 1;
                if (c0 > rowl) sacc[nt][0] = -1e30f;
                if (c1 > rowl) sacc[nt][1] = -1e30f;
                if (c0 > rowh) sacc[nt][2] = -1e30f;
                if (c1 > rowh) sacc[nt][3] = -1e30f;
            }
        }

        float mx_l = -1e30f, mx_h = -1e30f;
#pragma unroll
        for (int nt = 0; nt < 8; nt++) {
            mx_l = fmaxf(mx_l, fmaxf(sacc[nt][0], sacc[nt][1]));
            mx_h = fmaxf(mx_h, fmaxf(sacc[nt][2], sacc[nt][3]));
        }
#pragma unroll
        for (int sh = 1; sh < 4; sh <<= 1) {
            mx_l = fmaxf(mx_l, __shfl_xor_sync(0xffffffffu, mx_l, sh));
            mx_h = fmaxf(mx_h, __shfl_xor_sync(0xffffffffu, mx_h, sh));
        }
        const float mn_l = fmaxf(m_l, mx_l);
        const float mn_h = fmaxf(m_h, mx_h);
        const float sc_l = ex2(m_l - mn_l);
        const float sc_h = ex2(m_h - mn_h);
        m_l = mn_l;
        m_h = mn_h;

        // P frags directly via f16x2 exp (subtract folded into pack)
        uint32_t ph[4][4];
#pragma unroll
        for (int kf = 0; kf < 4; kf++) {
            ph[kf][0] = ex2h2(packh(sacc[2 * kf][0] - mn_l, sacc[2 * kf][1] - mn_l));
            ph[kf][1] = ex2h2(packh(sacc[2 * kf][2] - mn_h, sacc[2 * kf][3] - mn_h));
            ph[kf][2] = ex2h2(packh(sacc[2 * kf + 1][0] - mn_l, sacc[2 * kf + 1][1] - mn_l));
            ph[kf][3] = ex2h2(packh(sacc[2 * kf + 1][2] - mn_h, sacc[2 * kf + 1][3] - mn_h));
        }

        // row sums via ones-MMA (exact fp32 sums of actual fp16 P)
        float lacc[4] = { 0.f, 0.f, 0.f, 0.f };
#pragma unroll
        for (int kf = 0; kf < 4; kf++) hmma(lacc, ph[kf], bones);
        l_l = l_l * sc_l + lacc[0];
        l_h = l_h * sc_h + lacc[2];

#pragma unroll
        for (int i = 0; i < 16; i++) {
            o[i][0] *= sc_l; o[i][1] *= sc_l;
            o[i][2] *= sc_h; o[i][3] *= sc_h;
        }

#pragma unroll
        for (int kf = 0; kf < 4; kf++) {
            const uint32_t vrow = (uint32_t)(kf * 16) + (lane & 7) + (((uint32_t)lane >> 3) & 1) * 8;
#pragma unroll
            for (int np = 0; np < 8; np++) {
                const uint32_t hb = (uint32_t)np * 32 + khalf;
                uint32_t rv[4];
                ldsm4t(rv, st + FL_V + floff(vrow, hb));
                uint32_t b0[2] = { rv[0], rv[1] }, b1[2] = { rv[2], rv[3] };
                hmma(o[2 * np],     ph[kf], b0);
                hmma(o[2 * np + 1], ph[kf], b1);
            }
        }

        __syncthreads();
        issue(kt + 2);
    }

    const float inv_l = 1.f / l_l;
    const float inv_h = 1.f / l_h;
    const int grl = qt * 64 + w * 16 + rl;
    const int grh = grl + 8;
    const size_t basel = ((size_t)b * S_ + grl) * D_ + h * HD_;
    const size_t baseh = ((size_t)b * S_ + grh) * D_ + h * HD_;
#pragma unroll
    for (int nt = 0; nt < 16; nt++) {
        const int hd0 = nt * 8 + cq;
        *(uint32_t*)(oat + basel + hd0) = packh(o[nt][0] * inv_l, o[nt][1] * inv_l);
        *(uint32_t*)(oat + baseh + hd0) = packh(o[nt][2] * inv_h, o[nt][3] * inv_h);
    }
}

// ---------------- launcher ----------------
extern "C" void kernel_launch(void* const* d_in, const int* in_sizes, int n_in,
                              void* d_out, int out_size)
{
    (void)in_sizes; (void)n_in; (void)out_size;
    const float* x    = (const float*)d_in[0];
    const float* rsin = (const float*)d_in[2];
    const float* rcos = (const float*)d_in[3];
    const float* wqkv = (const float*)d_in[4];
    const float* wo   = (const float*)d_in[5];
    const float* n1   = (const float*)d_in[6];
    const float* n2   = (const float*)d_in[7];
    const float* wk   = (const float*)d_in[8];
    const float* wv   = (const float*)d_in[9];
    float* out = (float*)d_out;

    float* p_x1;
    __half *p_qh, *p_ql, *p_k, *p_v, *p_xn, *p_at, *p_h;
    __half *p_wqkv, *p_wo, *p_wk, *p_wv;
    cudaGetSymbolAddress((void**)&p_x1, g_x1);
    cudaGetSymbolAddress((void**)&p_qh, g_qh);
    cudaGetSymbolAddress((void**)&p_ql, g_ql);
    cudaGetSymbolAddress((void**)&p_k, g_k);
    cudaGetSymbolAddress((void**)&p_v, g_v);
    cudaGetSymbolAddress((void**)&p_xn, g_xn);
    cudaGetSymbolAddress((void**)&p_at, g_at);
    cudaGetSymbolAddress((void**)&p_h, g_h);
    cudaGetSymbolAddress((void**)&p_wqkv, g_wqkv);
    cudaGetSymbolAddress((void**)&p_wo, g_wo);
    cudaGetSymbolAddress((void**)&p_wk, g_wk);
    cudaGetSymbolAddress((void**)&p_wv, g_wv);

    cudaFuncSetAttribute(flash_kernel, cudaFuncAttributeMaxDynamicSharedMemorySize, FLASH_SMEM);
    cudaFuncSetAttribute(mma_gemm<1>, cudaFuncAttributeMaxDynamicSharedMemorySize, GEMM_SMEM);
    cudaFuncSetAttribute(mma_gemm<2>, cudaFuncAttributeMaxDynamicSharedMemorySize, GEMM_SMEM);
    cudaFuncSetAttribute(mma_gemm<3>, cudaFuncAttributeMaxDynamicSharedMemorySize, GEMM_SMEM);

    wcvt_kernel<<<(unsigned)((size_t)D_ * QKVN / 2048), 256>>>(wqkv, p_wqkv);
    wcvt_kernel<<<(unsigned)((size_t)D_ * D_ / 2048), 256>>>(wo, p_wo);
    wcvt_kernel<<<(unsigned)((size_t)D_ * FF_ / 2048), 256>>>(wk, p_wk);
    wcvt_kernel<<<(unsigned)((size_t)FF_ * D_ / 2048), 256>>>(wv, p_wv);

    // x1 = x + attn(rmsnorm(x))
    rmsnorm_h_kernel<<<M_, 256>>>(x, n1, p_xn);
    mma_gemm<3><<<dim3(QKVN / 256, M_ / 128), 256, GEMM_SMEM>>>(
        p_xn, p_wqkv, nullptr, nullptr, nullptr, rsin, rcos,
        p_qh, p_ql, p_k, p_v, QKVN, D_);
    flash_kernel<<<dim3(S_ / 64, QC_, B_), 128, FLASH_SMEM>>>(
        p_qh, p_ql, p_k, p_v, p_at);
    mma_gemm<1><<<dim3(D_ / 256, M_ / 128), 256, GEMM_SMEM>>>(
        p_at, p_wo, x, p_x1, nullptr, nullptr, nullptr,
        nullptr, nullptr, nullptr, nullptr, D_, D_);

    // out = x1 + ffn(rmsnorm(x1))
    rmsnorm_h_kernel<<<M_, 256>>>(p_x1, n2, p_xn);
    mma_gemm<2><<<dim3(FF_ / 256, M_ / 128), 256, GEMM_SMEM>>>(
        p_xn, p_wk, nullptr, nullptr, p_h, nullptr, nullptr,
        nullptr, nullptr, nullptr, nullptr, FF_, D_);
    mma_gemm<1><<<dim3(D_ / 256, M_ / 128), 256, GEMM_SMEM>>>(
        p_h, p_wv, p_x1, out, nullptr, nullptr, nullptr,
        nullptr, nullptr, nullptr, nullptr, D_, FF_);
}